// round 1
// baseline (speedup 1.0000x reference)
#include <cuda_runtime.h>
#include <math.h>

#define HIDDEN 4096
#define NHEADS 16
#define HDIM   256
#define ROT    64
#define BATCH  2
#define SEQ    2048
#define MROWS  (BATCH*SEQ)   /* 4096 */

// Scratch: Q, K, V, attn-out — 4 x 64 MB fp32
__device__ float g_scratch[4ull * MROWS * HIDDEN];

// ============================================================================
// SGEMM: C[M,N] = A[M,K] @ B[K,N], all row-major fp32.
// BM=BN=128, BK=16, 256 threads, 8x8 per-thread tile, float4 everywhere.
// ============================================================================
#define BM 128
#define BN 128
#define BKK 16
#define TM 8
#define TN 8

__global__ __launch_bounds__(256, 1) void sgemm_kernel(
    const float* __restrict__ A, const float* __restrict__ B,
    float* __restrict__ C, int M, int N, int K)
{
    __shared__ float As[BKK][BM];   // transposed A tile: As[k][m]
    __shared__ float Bs[BKK][BN];

    const int tid = threadIdx.x;
    const int tx = tid & 15;        // 0..15
    const int ty = tid >> 4;        // 0..15

    const float* Ab = A + (size_t)blockIdx.y * BM * K;
    const float* Bb = B + (size_t)blockIdx.x * BN;
    float*       Cb = C + (size_t)blockIdx.y * BM * N + (size_t)blockIdx.x * BN;

    const int aRow = tid >> 2;        // 0..63
    const int aCol = (tid & 3) << 2;  // 0,4,8,12
    const int bRow = tid >> 5;        // 0..7
    const int bCol = (tid & 31) << 2; // 0..124

    float acc[TM][TN];
    #pragma unroll
    for (int i = 0; i < TM; i++)
        #pragma unroll
        for (int j = 0; j < TN; j++) acc[i][j] = 0.0f;

    for (int k0 = 0; k0 < K; k0 += BKK) {
        // A tile (128x16) -> transposed smem
        #pragma unroll
        for (int p = 0; p < 2; p++) {
            int r = aRow + p * 64;
            float4 a = *(const float4*)(Ab + (size_t)r * K + k0 + aCol);
            As[aCol + 0][r] = a.x;
            As[aCol + 1][r] = a.y;
            As[aCol + 2][r] = a.z;
            As[aCol + 3][r] = a.w;
        }
        // B tile (16x128)
        #pragma unroll
        for (int p = 0; p < 2; p++) {
            int r = bRow + p * 8;
            *(float4*)(&Bs[r][bCol]) = *(const float4*)(Bb + (size_t)(k0 + r) * N + bCol);
        }
        __syncthreads();

        #pragma unroll
        for (int kk = 0; kk < BKK; kk++) {
            float ra[TM], rb[TN];
            *(float4*)(ra)     = *(const float4*)(&As[kk][ty * TM]);
            *(float4*)(ra + 4) = *(const float4*)(&As[kk][ty * TM + 4]);
            *(float4*)(rb)     = *(const float4*)(&Bs[kk][tx * TN]);
            *(float4*)(rb + 4) = *(const float4*)(&Bs[kk][tx * TN + 4]);
            #pragma unroll
            for (int i = 0; i < TM; i++)
                #pragma unroll
                for (int j = 0; j < TN; j++)
                    acc[i][j] = fmaf(ra[i], rb[j], acc[i][j]);
        }
        __syncthreads();
    }

    #pragma unroll
    for (int i = 0; i < TM; i++) {
        float* crow = Cb + (size_t)(ty * TM + i) * N + tx * TN;
        *(float4*)(crow)     = make_float4(acc[i][0], acc[i][1], acc[i][2], acc[i][3]);
        *(float4*)(crow + 4) = make_float4(acc[i][4], acc[i][5], acc[i][6], acc[i][7]);
    }
}

// ============================================================================
// RoPE (interleaved, first 64 dims of each head) applied in-place to Q and K.
// One thread per (b,s,h,pair). Angle in double to match numpy f64 einsum->f32.
// ============================================================================
__global__ __launch_bounds__(256) void rope_kernel(
    float* __restrict__ Q, float* __restrict__ K,
    const int* __restrict__ pos_ids)
{
    int idx = blockIdx.x * blockDim.x + threadIdx.x;   // B*S*H*32 = 2097152
    int j = idx & 31;
    int h = (idx >> 5) & 15;
    int s = (idx >> 9) & 2047;
    int b = idx >> 20;
    if (b >= BATCH) return;

    int pos = pos_ids[b * SEQ + s];
    // inv_freq = 10000^(-j/32)
    double inv = exp(-9.210340371976184 * (double)j / 32.0);
    float ang = (float)((double)pos * inv);
    float sv = sinf(ang), cv = cosf(ang);

    size_t base = (((size_t)(b * SEQ + s) * NHEADS) + h) * HDIM + 2 * j;
    float q0 = Q[base], q1 = Q[base + 1];
    Q[base]     = q0 * cv - q1 * sv;
    Q[base + 1] = q1 * cv + q0 * sv;
    float k0 = K[base], k1 = K[base + 1];
    K[base]     = k0 * cv - k1 * sv;
    K[base + 1] = k1 * cv + k0 * sv;
}

// ============================================================================
// Flash attention (fp32): BQ=64 queries x full D=256 per CTA, stream K/V in
// BKV=64 tiles with online softmax. Causal: kt loops 0..qt only.
// Thread map: 16x16 grid. Scores: thread owns 4x4 of S. Output: thread owns
// rows ty*4..+3, dims tx*16..+15 (acc[4][16]).
// smem: Q 64K + K 64K + V 64K + P 16K = 208 KB dynamic.
// ============================================================================
#define BQ  64
#define BKV 64

__global__ __launch_bounds__(256, 1) void attn_kernel(
    const float* __restrict__ Q, const float* __restrict__ K,
    const float* __restrict__ V, const float* __restrict__ amask,
    float* __restrict__ O)
{
    extern __shared__ float sm[];
    float* Qs = sm;                    // BQ  * HDIM
    float* Ks = Qs + BQ * HDIM;        // BKV * HDIM
    float* Vs = Ks + BKV * HDIM;       // BKV * HDIM
    float* Ps = Vs + BKV * HDIM;       // BQ * BKV

    const int qt = blockIdx.x;
    const int h  = blockIdx.y;
    const int b  = blockIdx.z;
    const int tid = threadIdx.x;
    const int tx = tid & 15;
    const int ty = tid >> 4;
    const int q0 = qt * BQ;
    const float scale = 1.0f / 16.0f;  // 1/sqrt(256)

    // Load Q tile (scaled)
    const float* Qg = Q + (((size_t)(b * SEQ + q0) * NHEADS) + h) * HDIM;
    for (int idx = tid; idx < BQ * (HDIM / 4); idx += 256) {
        int r = idx >> 6;          // HDIM/4 = 64
        int c4 = idx & 63;
        float4 v = *(const float4*)(Qg + (size_t)r * HIDDEN + c4 * 4);
        v.x *= scale; v.y *= scale; v.z *= scale; v.w *= scale;
        *(float4*)(Qs + r * HDIM + c4 * 4) = v;
    }

    float acc[4][16];
    #pragma unroll
    for (int i = 0; i < 4; i++)
        #pragma unroll
        for (int d = 0; d < 16; d++) acc[i][d] = 0.0f;
    float mrow[4] = {-1e30f, -1e30f, -1e30f, -1e30f};
    float lrow[4] = {0.f, 0.f, 0.f, 0.f};

    const int nkt = qt + 1;    // causal
    for (int kt = 0; kt < nkt; kt++) {
        const int k0 = kt * BKV;
        __syncthreads();   // previous PV done before K/V/P overwrite
        const float* Kg = K + (((size_t)(b * SEQ + k0) * NHEADS) + h) * HDIM;
        const float* Vg = V + (((size_t)(b * SEQ + k0) * NHEADS) + h) * HDIM;
        for (int idx = tid; idx < BKV * (HDIM / 4); idx += 256) {
            int r = idx >> 6;
            int c4 = idx & 63;
            *(float4*)(Ks + r * HDIM + c4 * 4) =
                *(const float4*)(Kg + (size_t)r * HIDDEN + c4 * 4);
            *(float4*)(Vs + r * HDIM + c4 * 4) =
                *(const float4*)(Vg + (size_t)r * HIDDEN + c4 * 4);
        }
        __syncthreads();

        // ---- scores S[4][4] ----
        float s[4][4];
        #pragma unroll
        for (int i = 0; i < 4; i++)
            #pragma unroll
            for (int j = 0; j < 4; j++) s[i][j] = 0.0f;

        const float4* Qs4 = (const float4*)Qs;
        const float4* Ks4 = (const float4*)Ks;
        #pragma unroll 4
        for (int d4 = 0; d4 < HDIM / 4; d4++) {
            float4 qv[4], kv[4];
            #pragma unroll
            for (int i = 0; i < 4; i++) qv[i] = Qs4[(ty * 4 + i) * (HDIM / 4) + d4];
            #pragma unroll
            for (int j = 0; j < 4; j++) kv[j] = Ks4[(tx * 4 + j) * (HDIM / 4) + d4];
            #pragma unroll
            for (int i = 0; i < 4; i++)
                #pragma unroll
                for (int j = 0; j < 4; j++) {
                    s[i][j] = fmaf(qv[i].x, kv[j].x, s[i][j]);
                    s[i][j] = fmaf(qv[i].y, kv[j].y, s[i][j]);
                    s[i][j] = fmaf(qv[i].z, kv[j].z, s[i][j]);
                    s[i][j] = fmaf(qv[i].w, kv[j].w, s[i][j]);
                }
        }

        // ---- mask (causal + padding) ----
        #pragma unroll
        for (int j = 0; j < 4; j++) {
            int kg = k0 + tx * 4 + j;
            bool padok = (amask[b * SEQ + kg] > 0.0f);
            #pragma unroll
            for (int i = 0; i < 4; i++) {
                int qg = q0 + ty * 4 + i;
                if (kg > qg || !padok) s[i][j] = -1e30f;
            }
        }

        // ---- online softmax update ----
        #pragma unroll
        for (int i = 0; i < 4; i++) {
            float mt = fmaxf(fmaxf(s[i][0], s[i][1]), fmaxf(s[i][2], s[i][3]));
            #pragma unroll
            for (int off = 1; off < 16; off <<= 1)
                mt = fmaxf(mt, __shfl_xor_sync(0xffffffffu, mt, off));
            float mnew = fmaxf(mrow[i], mt);
            float corr = __expf(mrow[i] - mnew);
            float rs = 0.0f;
            #pragma unroll
            for (int j = 0; j < 4; j++) {
                s[i][j] = __expf(s[i][j] - mnew);
                rs += s[i][j];
            }
            #pragma unroll
            for (int off = 1; off < 16; off <<= 1)
                rs += __shfl_xor_sync(0xffffffffu, rs, off);
            lrow[i] = lrow[i] * corr + rs;
            mrow[i] = mnew;
            #pragma unroll
            for (int d = 0; d < 16; d++) acc[i][d] *= corr;
            #pragma unroll
            for (int j = 0; j < 4; j++)
                Ps[(ty * 4 + i) * BKV + tx * 4 + j] = s[i][j];
        }
        __syncthreads();

        // ---- PV accumulate ----
        const float4* Vs4 = (const float4*)Vs;
        #pragma unroll 2
        for (int kc = 0; kc < BKV; kc++) {
            float p[4];
            #pragma unroll
            for (int i = 0; i < 4; i++) p[i] = Ps[(ty * 4 + i) * BKV + kc];
            #pragma unroll
            for (int dd4 = 0; dd4 < 4; dd4++) {
                float4 v = Vs4[kc * (HDIM / 4) + tx * 4 + dd4];
                #pragma unroll
                for (int i = 0; i < 4; i++) {
                    acc[i][dd4 * 4 + 0] = fmaf(p[i], v.x, acc[i][dd4 * 4 + 0]);
                    acc[i][dd4 * 4 + 1] = fmaf(p[i], v.y, acc[i][dd4 * 4 + 1]);
                    acc[i][dd4 * 4 + 2] = fmaf(p[i], v.z, acc[i][dd4 * 4 + 2]);
                    acc[i][dd4 * 4 + 3] = fmaf(p[i], v.w, acc[i][dd4 * 4 + 3]);
                }
            }
        }
    }

    // ---- write O (normalized) in [B,S,H,D] layout ----
    float* Og = O + (((size_t)(b * SEQ + q0) * NHEADS) + h) * HDIM;
    #pragma unroll
    for (int i = 0; i < 4; i++) {
        int r = ty * 4 + i;
        float inv_l = 1.0f / lrow[i];
        #pragma unroll
        for (int dd4 = 0; dd4 < 4; dd4++) {
            float4 v;
            v.x = acc[i][dd4 * 4 + 0] * inv_l;
            v.y = acc[i][dd4 * 4 + 1] * inv_l;
            v.z = acc[i][dd4 * 4 + 2] * inv_l;
            v.w = acc[i][dd4 * 4 + 3] * inv_l;
            *(float4*)(Og + (size_t)r * HIDDEN + tx * 16 + dd4 * 4) = v;
        }
    }
}

// ============================================================================
// Launch
// ============================================================================
extern "C" void kernel_launch(void* const* d_in, const int* in_sizes, int n_in,
                              void* d_out, int out_size)
{
    const float* X    = (const float*)d_in[0];   // hidden_states [2,2048,4096]
    const float* msk  = (const float*)d_in[1];   // attention_mask [2,2048]
    const int*   pos  = (const int*)  d_in[2];   // position_ids [2,2048]
    const float* Wq   = (const float*)d_in[3];
    const float* Wk   = (const float*)d_in[4];
    const float* Wv   = (const float*)d_in[5];
    const float* Wo   = (const float*)d_in[6];
    float* out = (float*)d_out;

    float* scratch = nullptr;
    cudaGetSymbolAddress((void**)&scratch, g_scratch);
    float* Qb = scratch;
    float* Kb = scratch + (size_t)1 * MROWS * HIDDEN;
    float* Vb = scratch + (size_t)2 * MROWS * HIDDEN;
    float* Ob = scratch + (size_t)3 * MROWS * HIDDEN;

    dim3 gemm_grid(HIDDEN / BN, MROWS / BM);   // (32, 32)
    sgemm_kernel<<<gemm_grid, 256>>>(X, Wq, Qb, MROWS, HIDDEN, HIDDEN);
    sgemm_kernel<<<gemm_grid, 256>>>(X, Wk, Kb, MROWS, HIDDEN, HIDDEN);
    sgemm_kernel<<<gemm_grid, 256>>>(X, Wv, Vb, MROWS, HIDDEN, HIDDEN);

    rope_kernel<<<(BATCH * SEQ * NHEADS * (ROT / 2)) / 256, 256>>>(Qb, Kb, pos);

    int smem = (3 * BKV * HDIM + BQ * BKV) * (int)sizeof(float);  // 212992
    cudaFuncSetAttribute(attn_kernel,
                         cudaFuncAttributeMaxDynamicSharedMemorySize, smem);
    dim3 attn_grid(SEQ / BQ, NHEADS, BATCH);   // (32, 16, 2)
    attn_kernel<<<attn_grid, 256, smem>>>(Qb, Kb, Vb, msk, Ob);

    sgemm_kernel<<<gemm_grid, 256>>>(Ob, Wo, out, MROWS, HIDDEN, HIDDEN);
}

// round 3
// speedup vs baseline: 1.5771x; 1.5771x over previous
#include <cuda_runtime.h>
#include <cuda_bf16.h>
#include <math.h>
#include <stdint.h>

#define HIDDEN 4096
#define NHEADS 16
#define HDIM   256
#define ROT    64
#define BATCH  2
#define SEQ    2048
#define MROWS  (BATCH*SEQ)   /* 4096 */

// fp32 scratch: Q, K, V
__device__ float g_f32[3ull * MROWS * HIDDEN];
// bf16 scratch slots (each 4096*4096):
//  0: Xh  1: Xl  2: Oh  3: Ol
//  4: Wq_h 5: Wq_l 6: Wk_h 7: Wk_l 8: Wv_h 9: Wv_l 10: Wo_h 11: Wo_l
__device__ __nv_bfloat16 g_bf16[12ull * MROWS * HIDDEN];

#define SLOT ((size_t)MROWS * HIDDEN)

// ============================================================================
// PTX helpers (arch-neutral: sm_80+ features only — the harness builds via
// virtual arch compute_103, so no tcgen05/TMEM/'a'-suffix features)
// ============================================================================
__device__ __forceinline__ uint32_t smem_u32(const void* p) {
    uint32_t a;
    asm("{ .reg .u64 t; cvta.to.shared.u64 t, %1; cvt.u32.u64 %0, t; }"
        : "=r"(a) : "l"(p));
    return a;
}

__device__ __forceinline__ void cp_async16(uint32_t dst, const void* src) {
    asm volatile("cp.async.cg.shared.global [%0], [%1], 16;"
                 :: "r"(dst), "l"(src));
}
#define CP_COMMIT() asm volatile("cp.async.commit_group;" ::: "memory")
#define CP_WAIT(n)  asm volatile("cp.async.wait_group %0;" :: "n"(n) : "memory")

__device__ __forceinline__ void ldsm_x4(uint32_t& r0, uint32_t& r1,
                                        uint32_t& r2, uint32_t& r3,
                                        uint32_t addr) {
    asm volatile("ldmatrix.sync.aligned.m8n8.x4.shared.b16 {%0,%1,%2,%3}, [%4];"
                 : "=r"(r0), "=r"(r1), "=r"(r2), "=r"(r3) : "r"(addr));
}

__device__ __forceinline__ void mma_bf16(float c[4],
                                         uint32_t a0, uint32_t a1,
                                         uint32_t a2, uint32_t a3,
                                         uint32_t b0, uint32_t b1) {
    asm volatile(
        "mma.sync.aligned.m16n8k16.row.col.f32.bf16.bf16.f32 "
        "{%0,%1,%2,%3}, {%4,%5,%6,%7}, {%8,%9}, {%0,%1,%2,%3};"
        : "+f"(c[0]), "+f"(c[1]), "+f"(c[2]), "+f"(c[3])
        : "r"(a0), "r"(a1), "r"(a2), "r"(a3), "r"(b0), "r"(b1));
}

// ============================================================================
// Split kernels: fp32 -> (hi, lo) bf16
// ============================================================================
__global__ __launch_bounds__(256) void split_rows_kernel(
    const float* __restrict__ X, __nv_bfloat16* __restrict__ H,
    __nv_bfloat16* __restrict__ L)
{
    size_t i = ((size_t)blockIdx.x * 256 + threadIdx.x) * 4;
    float4 v = *(const float4*)(X + i);
    float f[4] = {v.x, v.y, v.z, v.w};
    __nv_bfloat16 hh[4], ll[4];
    #pragma unroll
    for (int j = 0; j < 4; j++) {
        hh[j] = __float2bfloat16(f[j]);
        ll[j] = __float2bfloat16(f[j] - __bfloat162float(hh[j]));
    }
    *(uint2*)(H + i) = *(uint2*)hh;
    *(uint2*)(L + i) = *(uint2*)ll;
}

// Transpose + split: W fp32 [K,N] row-major -> H/L bf16 [N,K] row-major
__global__ __launch_bounds__(256) void split_T_kernel(
    const float* __restrict__ W, __nv_bfloat16* __restrict__ H,
    __nv_bfloat16* __restrict__ L)
{
    __shared__ float t[32][33];
    const int n0 = blockIdx.x * 32;
    const int k0 = blockIdx.y * 32;
    const int tx = threadIdx.x & 31;
    const int ty = threadIdx.x >> 5;
    #pragma unroll
    for (int j = ty; j < 32; j += 8)
        t[j][tx] = W[(size_t)(k0 + j) * HIDDEN + n0 + tx];
    __syncthreads();
    #pragma unroll
    for (int j = ty; j < 32; j += 8) {
        float x = t[tx][j];
        __nv_bfloat16 h = __float2bfloat16(x);
        __nv_bfloat16 l = __float2bfloat16(x - __bfloat162float(h));
        size_t off = (size_t)(n0 + j) * HIDDEN + k0 + tx;
        H[off] = h;
        L[off] = l;
    }
}

// ============================================================================
// bf16x3 tensor-core GEMM via mma.sync: C[M,N] f32 = (Ah+Al) @ (Bh+Bl)^T
// A: [M,K] bf16 row-major (hi,lo); B: [N,K] bf16 row-major (hi,lo).
// BM=BN=128, BK=32, 256 threads (8 warps, 2x4), warp tile 64x32.
// Smem: 4 operand tiles x 128 rows x 40 bf16 (80B stride, conflict-free
// ldmatrix), double-buffered with cp.async.
// ============================================================================
#define GBK     32
#define TILE_B  10240        /* 128 * 80 bytes */
#define STAGE_B (4 * TILE_B) /* 40960 */

__global__ __launch_bounds__(256, 1) void gemm_mma_kernel(
    const __nv_bfloat16* __restrict__ Ah, const __nv_bfloat16* __restrict__ Al,
    const __nv_bfloat16* __restrict__ Bh, const __nv_bfloat16* __restrict__ Bl,
    float* __restrict__ C)
{
    extern __shared__ char smg[];
    const uint32_t sb = smem_u32(smg);
    const int tid  = threadIdx.x;
    const int wid  = tid >> 5;
    const int lane = tid & 31;
    const int wm = wid >> 2;   // 0..1 -> m offset wm*64
    const int wn = wid & 3;    // 0..3 -> n offset wn*32
    const int rowbase = blockIdx.y * 128;
    const int colbase = blockIdx.x * 128;

    const __nv_bfloat16* bases[4];
    bases[0] = Ah + (size_t)rowbase * HIDDEN;
    bases[1] = Al + (size_t)rowbase * HIDDEN;
    bases[2] = Bh + (size_t)colbase * HIDDEN;
    bases[3] = Bl + (size_t)colbase * HIDDEN;

    float acc[4][4][4];
    #pragma unroll
    for (int i = 0; i < 4; i++)
        #pragma unroll
        for (int j = 0; j < 4; j++)
            #pragma unroll
            for (int q = 0; q < 4; q++) acc[i][j][q] = 0.0f;

    const int NCH = HIDDEN / GBK;   // 128

    // ---- prefetch stage 0 ----
    {
        #pragma unroll
        for (int it = 0; it < 8; it++) {
            int t = tid + it * 256;        // 0..2047
            int tile = t >> 9;             // 0..3
            int r    = (t >> 2) & 127;
            int ch   = t & 3;
            const void* g = bases[tile] + (size_t)r * HIDDEN + ch * 8;
            uint32_t d = sb + tile * TILE_B + r * 80 + ch * 16;
            cp_async16(d, g);
        }
        CP_COMMIT();
    }

    for (int c = 0; c < NCH; c++) {
        const int p = c & 1;
        if (c + 1 < NCH) {
            const int kb = (c + 1) * GBK;
            #pragma unroll
            for (int it = 0; it < 8; it++) {
                int t = tid + it * 256;
                int tile = t >> 9;
                int r    = (t >> 2) & 127;
                int ch   = t & 3;
                const void* g = bases[tile] + (size_t)r * HIDDEN + kb + ch * 8;
                uint32_t d = sb + (p ^ 1) * STAGE_B + tile * TILE_B + r * 80 + ch * 16;
                cp_async16(d, g);
            }
            CP_COMMIT();
            CP_WAIT(1);
        } else {
            CP_WAIT(0);
        }
        __syncthreads();

        const uint32_t At_h = sb + p * STAGE_B;
        const uint32_t At_l = At_h + TILE_B;
        const uint32_t Bt_h = At_h + 2 * TILE_B;
        const uint32_t Bt_l = At_h + 3 * TILE_B;

        const int arow = lane & 15;
        const int aoff = ((lane >> 4) & 1) * 16;
        const int brow = (lane & 7) + ((lane >> 4) & 1) * 8;
        const int boff = ((lane >> 3) & 1) * 16;

        #pragma unroll
        for (int ks = 0; ks < 2; ks++) {
            const int kbyte = ks * 32;
            uint32_t ah[4][4], al[4][4];
            #pragma unroll
            for (int mi = 0; mi < 4; mi++) {
                uint32_t addr = At_h + (wm * 64 + mi * 16 + arow) * 80 + kbyte + aoff;
                ldsm_x4(ah[mi][0], ah[mi][1], ah[mi][2], ah[mi][3], addr);
            }
            #pragma unroll
            for (int mi = 0; mi < 4; mi++) {
                uint32_t addr = At_l + (wm * 64 + mi * 16 + arow) * 80 + kbyte + aoff;
                ldsm_x4(al[mi][0], al[mi][1], al[mi][2], al[mi][3], addr);
            }
            uint32_t bh[4][2], bl[4][2];
            #pragma unroll
            for (int nf2 = 0; nf2 < 2; nf2++) {
                uint32_t r0, r1, r2, r3;
                uint32_t addr = Bt_h + (wn * 32 + nf2 * 16 + brow) * 80 + kbyte + boff;
                ldsm_x4(r0, r1, r2, r3, addr);
                bh[nf2 * 2][0] = r0; bh[nf2 * 2][1] = r1;
                bh[nf2 * 2 + 1][0] = r2; bh[nf2 * 2 + 1][1] = r3;
                addr = Bt_l + (wn * 32 + nf2 * 16 + brow) * 80 + kbyte + boff;
                ldsm_x4(r0, r1, r2, r3, addr);
                bl[nf2 * 2][0] = r0; bl[nf2 * 2][1] = r1;
                bl[nf2 * 2 + 1][0] = r2; bl[nf2 * 2 + 1][1] = r3;
            }
            #pragma unroll
            for (int mi = 0; mi < 4; mi++)
                #pragma unroll
                for (int nf = 0; nf < 4; nf++) {
                    mma_bf16(acc[mi][nf], ah[mi][0], ah[mi][1], ah[mi][2], ah[mi][3],
                             bh[nf][0], bh[nf][1]);
                    mma_bf16(acc[mi][nf], ah[mi][0], ah[mi][1], ah[mi][2], ah[mi][3],
                             bl[nf][0], bl[nf][1]);
                    mma_bf16(acc[mi][nf], al[mi][0], al[mi][1], al[mi][2], al[mi][3],
                             bh[nf][0], bh[nf][1]);
                }
        }
        __syncthreads();
    }

    // ---- epilogue ----
    const int g = lane >> 2;
    const int t = lane & 3;
    #pragma unroll
    for (int mi = 0; mi < 4; mi++) {
        #pragma unroll
        for (int nf = 0; nf < 4; nf++) {
            float* base = C + (size_t)(rowbase + wm * 64 + mi * 16 + g) * HIDDEN
                            + colbase + wn * 32 + nf * 8 + t * 2;
            *(float2*)base = make_float2(acc[mi][nf][0], acc[mi][nf][1]);
            *(float2*)(base + (size_t)8 * HIDDEN) = make_float2(acc[mi][nf][2], acc[mi][nf][3]);
        }
    }
}

// ============================================================================
// RoPE
// ============================================================================
__global__ __launch_bounds__(256) void rope_kernel(
    float* __restrict__ Q, float* __restrict__ K,
    const int* __restrict__ pos_ids)
{
    int idx = blockIdx.x * blockDim.x + threadIdx.x;
    int j = idx & 31;
    int h = (idx >> 5) & 15;
    int s = (idx >> 9) & 2047;
    int b = idx >> 20;
    if (b >= BATCH) return;

    int pos = pos_ids[b * SEQ + s];
    double inv = exp(-9.210340371976184 * (double)j / 32.0);
    float ang = (float)((double)pos * inv);
    float sv = sinf(ang), cv = cosf(ang);

    size_t base = (((size_t)(b * SEQ + s) * NHEADS) + h) * HDIM + 2 * j;
    float q0 = Q[base], q1 = Q[base + 1];
    Q[base]     = q0 * cv - q1 * sv;
    Q[base + 1] = q1 * cv + q0 * sv;
    float k0 = K[base], k1 = K[base + 1];
    K[base]     = k0 * cv - k1 * sv;
    K[base + 1] = k1 * cv + k0 * sv;
}

// ============================================================================
// Flash attention (fp32), emits bf16 hi/lo output
// ============================================================================
#define BQ  64
#define BKV 64

__global__ __launch_bounds__(256, 1) void attn_kernel(
    const float* __restrict__ Q, const float* __restrict__ K,
    const float* __restrict__ V, const float* __restrict__ amask,
    __nv_bfloat16* __restrict__ Oh, __nv_bfloat16* __restrict__ Ol)
{
    extern __shared__ float smf[];
    float* Qs = smf;
    float* Ks = Qs + BQ * HDIM;
    float* Vs = Ks + BKV * HDIM;
    float* Ps = Vs + BKV * HDIM;

    const int qt = blockIdx.x;
    const int h  = blockIdx.y;
    const int b  = blockIdx.z;
    const int tid = threadIdx.x;
    const int tx = tid & 15;
    const int ty = tid >> 4;
    const int q0 = qt * BQ;
    const float scale = 1.0f / 16.0f;

    const float* Qg = Q + (((size_t)(b * SEQ + q0) * NHEADS) + h) * HDIM;
    for (int idx = tid; idx < BQ * (HDIM / 4); idx += 256) {
        int r = idx >> 6;
        int c4 = idx & 63;
        float4 v = *(const float4*)(Qg + (size_t)r * HIDDEN + c4 * 4);
        v.x *= scale; v.y *= scale; v.z *= scale; v.w *= scale;
        *(float4*)(Qs + r * HDIM + c4 * 4) = v;
    }

    float acc[4][16];
    #pragma unroll
    for (int i = 0; i < 4; i++)
        #pragma unroll
        for (int d = 0; d < 16; d++) acc[i][d] = 0.0f;
    float mrow[4] = {-1e30f, -1e30f, -1e30f, -1e30f};
    float lrow[4] = {0.f, 0.f, 0.f, 0.f};

    const int nkt = qt + 1;
    for (int kt = 0; kt < nkt; kt++) {
        const int k0 = kt * BKV;
        __syncthreads();
        const float* Kg = K + (((size_t)(b * SEQ + k0) * NHEADS) + h) * HDIM;
        const float* Vg = V + (((size_t)(b * SEQ + k0) * NHEADS) + h) * HDIM;
        for (int idx = tid; idx < BKV * (HDIM / 4); idx += 256) {
            int r = idx >> 6;
            int c4 = idx & 63;
            *(float4*)(Ks + r * HDIM + c4 * 4) =
                *(const float4*)(Kg + (size_t)r * HIDDEN + c4 * 4);
            *(float4*)(Vs + r * HDIM + c4 * 4) =
                *(const float4*)(Vg + (size_t)r * HIDDEN + c4 * 4);
        }
        __syncthreads();

        float s[4][4];
        #pragma unroll
        for (int i = 0; i < 4; i++)
            #pragma unroll
            for (int j = 0; j < 4; j++) s[i][j] = 0.0f;

        const float4* Qs4 = (const float4*)Qs;
        const float4* Ks4 = (const float4*)Ks;
        #pragma unroll 4
        for (int d4 = 0; d4 < HDIM / 4; d4++) {
            float4 qv[4], kv[4];
            #pragma unroll
            for (int i = 0; i < 4; i++) qv[i] = Qs4[(ty * 4 + i) * (HDIM / 4) + d4];
            #pragma unroll
            for (int j = 0; j < 4; j++) kv[j] = Ks4[(tx * 4 + j) * (HDIM / 4) + d4];
            #pragma unroll
            for (int i = 0; i < 4; i++)
                #pragma unroll
                for (int j = 0; j < 4; j++) {
                    s[i][j] = fmaf(qv[i].x, kv[j].x, s[i][j]);
                    s[i][j] = fmaf(qv[i].y, kv[j].y, s[i][j]);
                    s[i][j] = fmaf(qv[i].z, kv[j].z, s[i][j]);
                    s[i][j] = fmaf(qv[i].w, kv[j].w, s[i][j]);
                }
        }

        #pragma unroll
        for (int j = 0; j < 4; j++) {
            int kg = k0 + tx * 4 + j;
            bool padok = (amask[b * SEQ + kg] > 0.0f);
            #pragma unroll
            for (int i = 0; i < 4; i++) {
                int qg = q0 + ty * 4 + i;
                if (kg > qg || !padok) s[i][j] = -1e30f;
            }
        }

        #pragma unroll
        for (int i = 0; i < 4; i++) {
            float mt = fmaxf(fmaxf(s[i][0], s[i][1]), fmaxf(s[i][2], s[i][3]));
            #pragma unroll
            for (int off = 1; off < 16; off <<= 1)
                mt = fmaxf(mt, __shfl_xor_sync(0xffffffffu, mt, off));
            float mnew = fmaxf(mrow[i], mt);
            float corr = __expf(mrow[i] - mnew);
            float rs = 0.0f;
            #pragma unroll
            for (int j = 0; j < 4; j++) {
                s[i][j] = __expf(s[i][j] - mnew);
                rs += s[i][j];
            }
            #pragma unroll
            for (int off = 1; off < 16; off <<= 1)
                rs += __shfl_xor_sync(0xffffffffu, rs, off);
            lrow[i] = lrow[i] * corr + rs;
            mrow[i] = mnew;
            #pragma unroll
            for (int d = 0; d < 16; d++) acc[i][d] *= corr;
            #pragma unroll
            for (int j = 0; j < 4; j++)
                Ps[(ty * 4 + i) * BKV + tx * 4 + j] = s[i][j];
        }
        __syncthreads();

        const float4* Vs4 = (const float4*)Vs;
        #pragma unroll 2
        for (int kc = 0; kc < BKV; kc++) {
            float pv[4];
            #pragma unroll
            for (int i = 0; i < 4; i++) pv[i] = Ps[(ty * 4 + i) * BKV + kc];
            #pragma unroll
            for (int dd4 = 0; dd4 < 4; dd4++) {
                float4 v = Vs4[kc * (HDIM / 4) + tx * 4 + dd4];
                #pragma unroll
                for (int i = 0; i < 4; i++) {
                    acc[i][dd4 * 4 + 0] = fmaf(pv[i], v.x, acc[i][dd4 * 4 + 0]);
                    acc[i][dd4 * 4 + 1] = fmaf(pv[i], v.y, acc[i][dd4 * 4 + 1]);
                    acc[i][dd4 * 4 + 2] = fmaf(pv[i], v.z, acc[i][dd4 * 4 + 2]);
                    acc[i][dd4 * 4 + 3] = fmaf(pv[i], v.w, acc[i][dd4 * 4 + 3]);
                }
            }
        }
    }

    size_t obase = ((size_t)(b * SEQ + q0)) * HIDDEN + h * HDIM;
    #pragma unroll
    for (int i = 0; i < 4; i++) {
        int r = ty * 4 + i;
        float inv_l = 1.0f / lrow[i];
        __nv_bfloat16 hh[16], ll[16];
        #pragma unroll
        for (int d = 0; d < 16; d++) {
            float val = acc[i][d] * inv_l;
            hh[d] = __float2bfloat16(val);
            ll[d] = __float2bfloat16(val - __bfloat162float(hh[d]));
        }
        size_t off = obase + (size_t)r * HIDDEN + tx * 16;
        #pragma unroll
        for (int q = 0; q < 16; q += 4) {
            *(uint2*)(Oh + off + q) = *(uint2*)(hh + q);
            *(uint2*)(Ol + off + q) = *(uint2*)(ll + q);
        }
    }
}

// ============================================================================
// Launch
// ============================================================================
extern "C" void kernel_launch(void* const* d_in, const int* in_sizes, int n_in,
                              void* d_out, int out_size)
{
    const float* X   = (const float*)d_in[0];
    const float* msk = (const float*)d_in[1];
    const int*   pos = (const int*)  d_in[2];
    const float* Wq  = (const float*)d_in[3];
    const float* Wk  = (const float*)d_in[4];
    const float* Wv  = (const float*)d_in[5];
    const float* Wo  = (const float*)d_in[6];
    float* out = (float*)d_out;

    float* f32 = nullptr;
    __nv_bfloat16* bf = nullptr;
    cudaGetSymbolAddress((void**)&f32, g_f32);
    cudaGetSymbolAddress((void**)&bf, g_bf16);

    float* Qb = f32;
    float* Kb = f32 + 1 * SLOT;
    float* Vb = f32 + 2 * SLOT;

    __nv_bfloat16* Xh  = bf + 0 * SLOT;
    __nv_bfloat16* Xl  = bf + 1 * SLOT;
    __nv_bfloat16* Oh  = bf + 2 * SLOT;
    __nv_bfloat16* Ol  = bf + 3 * SLOT;
    __nv_bfloat16* Wqh = bf + 4 * SLOT;  __nv_bfloat16* Wql = bf + 5 * SLOT;
    __nv_bfloat16* Wkh = bf + 6 * SLOT;  __nv_bfloat16* Wkl = bf + 7 * SLOT;
    __nv_bfloat16* Wvh = bf + 8 * SLOT;  __nv_bfloat16* Wvl = bf + 9 * SLOT;
    __nv_bfloat16* Woh = bf + 10 * SLOT; __nv_bfloat16* Wol = bf + 11 * SLOT;

    int split_blocks = (int)(SLOT / (256 * 4));
    split_rows_kernel<<<split_blocks, 256>>>(X, Xh, Xl);
    dim3 tgrid(HIDDEN / 32, HIDDEN / 32);
    split_T_kernel<<<tgrid, 256>>>(Wq, Wqh, Wql);
    split_T_kernel<<<tgrid, 256>>>(Wk, Wkh, Wkl);
    split_T_kernel<<<tgrid, 256>>>(Wv, Wvh, Wvl);
    split_T_kernel<<<tgrid, 256>>>(Wo, Woh, Wol);

    int gsmem = 2 * STAGE_B;   // 81920
    cudaFuncSetAttribute(gemm_mma_kernel,
                         cudaFuncAttributeMaxDynamicSharedMemorySize, gsmem);
    dim3 ggrid(HIDDEN / 128, MROWS / 128);   // 32 x 32
    gemm_mma_kernel<<<ggrid, 256, gsmem>>>(Xh, Xl, Wqh, Wql, Qb);
    gemm_mma_kernel<<<ggrid, 256, gsmem>>>(Xh, Xl, Wkh, Wkl, Kb);
    gemm_mma_kernel<<<ggrid, 256, gsmem>>>(Xh, Xl, Wvh, Wvl, Vb);

    rope_kernel<<<(BATCH * SEQ * NHEADS * (ROT / 2)) / 256, 256>>>(Qb, Kb, pos);

    int asmem = (3 * BKV * HDIM + BQ * BKV) * (int)sizeof(float);
    cudaFuncSetAttribute(attn_kernel,
                         cudaFuncAttributeMaxDynamicSharedMemorySize, asmem);
    dim3 agrid(SEQ / BQ, NHEADS, BATCH);
    attn_kernel<<<agrid, 256, asmem>>>(Qb, Kb, Vb, msk, Oh, Ol);

    gemm_mma_kernel<<<ggrid, 256, gsmem>>>(Oh, Ol, Woh, Wol, out);
}

// round 4
// speedup vs baseline: 3.7397x; 2.3712x over previous
#include <cuda_runtime.h>
#include <cuda_bf16.h>
#include <math.h>
#include <stdint.h>

#define HIDDEN 4096
#define NHEADS 16
#define HDIM   256
#define ROT    64
#define BATCH  2
#define SEQ    2048
#define MROWS  (BATCH*SEQ)   /* 4096 */

// fp32 scratch: Q, K, V
__device__ float g_f32[3ull * MROWS * HIDDEN];
// bf16 scratch slots (each 4096*4096 = 32 MB):
//  0:Xh 1:Xl 2:Oh 3:Ol 4:Wq_h 5:Wq_l 6:Wk_h 7:Wk_l 8:Wv_h 9:Wv_l 10:Wo_h 11:Wo_l
// 12:Qh 13:Ql 14:Kh 15:Kl 16:Vh 17:Vl
__device__ __nv_bfloat16 g_bf16[18ull * MROWS * HIDDEN];

#define SLOT ((size_t)MROWS * HIDDEN)

// ============================================================================
// PTX helpers (arch-neutral sm_80/sm_90 features only — harness builds via
// virtual arch compute_103, no tcgen05/'a'-suffix features)
// ============================================================================
__device__ __forceinline__ uint32_t smem_u32(const void* p) {
    uint32_t a;
    asm("{ .reg .u64 t; cvta.to.shared.u64 t, %1; cvt.u32.u64 %0, t; }"
        : "=r"(a) : "l"(p));
    return a;
}

__device__ __forceinline__ void cp_async16(uint32_t dst, const void* src) {
    asm volatile("cp.async.cg.shared.global [%0], [%1], 16;"
                 :: "r"(dst), "l"(src));
}
#define CP_COMMIT() asm volatile("cp.async.commit_group;" ::: "memory")
#define CP_WAIT(n)  asm volatile("cp.async.wait_group %0;" :: "n"(n) : "memory")

__device__ __forceinline__ void ldsm_x4(uint32_t& r0, uint32_t& r1,
                                        uint32_t& r2, uint32_t& r3,
                                        uint32_t addr) {
    asm volatile("ldmatrix.sync.aligned.m8n8.x4.shared.b16 {%0,%1,%2,%3}, [%4];"
                 : "=r"(r0), "=r"(r1), "=r"(r2), "=r"(r3) : "r"(addr));
}
__device__ __forceinline__ void ldsm_x4_t(uint32_t& r0, uint32_t& r1,
                                          uint32_t& r2, uint32_t& r3,
                                          uint32_t addr) {
    asm volatile("ldmatrix.sync.aligned.m8n8.x4.trans.shared.b16 {%0,%1,%2,%3}, [%4];"
                 : "=r"(r0), "=r"(r1), "=r"(r2), "=r"(r3) : "r"(addr));
}

__device__ __forceinline__ void mma_bf16(float c[4],
                                         uint32_t a0, uint32_t a1,
                                         uint32_t a2, uint32_t a3,
                                         uint32_t b0, uint32_t b1) {
    asm volatile(
        "mma.sync.aligned.m16n8k16.row.col.f32.bf16.bf16.f32 "
        "{%0,%1,%2,%3}, {%4,%5,%6,%7}, {%8,%9}, {%0,%1,%2,%3};"
        : "+f"(c[0]), "+f"(c[1]), "+f"(c[2]), "+f"(c[3])
        : "r"(a0), "r"(a1), "r"(a2), "r"(a3), "r"(b0), "r"(b1));
}

__device__ __forceinline__ uint32_t pack_bf16(float a, float b) {
    __nv_bfloat162 t = __floats2bfloat162_rn(a, b);
    return *(uint32_t*)&t;
}

// ============================================================================
// Split kernels: fp32 -> (hi, lo) bf16
// ============================================================================
__global__ __launch_bounds__(256) void split_rows_kernel(
    const float* __restrict__ X, __nv_bfloat16* __restrict__ H,
    __nv_bfloat16* __restrict__ L)
{
    size_t i = ((size_t)blockIdx.x * 256 + threadIdx.x) * 4;
    float4 v = *(const float4*)(X + i);
    float f[4] = {v.x, v.y, v.z, v.w};
    __nv_bfloat16 hh[4], ll[4];
    #pragma unroll
    for (int j = 0; j < 4; j++) {
        hh[j] = __float2bfloat16(f[j]);
        ll[j] = __float2bfloat16(f[j] - __bfloat162float(hh[j]));
    }
    *(uint2*)(H + i) = *(uint2*)hh;
    *(uint2*)(L + i) = *(uint2*)ll;
}

// Transpose + split: W fp32 [K,N] row-major -> H/L bf16 [N,K] row-major
__global__ __launch_bounds__(256) void split_T_kernel(
    const float* __restrict__ W, __nv_bfloat16* __restrict__ H,
    __nv_bfloat16* __restrict__ L)
{
    __shared__ float t[32][33];
    const int n0 = blockIdx.x * 32;
    const int k0 = blockIdx.y * 32;
    const int tx = threadIdx.x & 31;
    const int ty = threadIdx.x >> 5;
    #pragma unroll
    for (int j = ty; j < 32; j += 8)
        t[j][tx] = W[(size_t)(k0 + j) * HIDDEN + n0 + tx];
    __syncthreads();
    #pragma unroll
    for (int j = ty; j < 32; j += 8) {
        float x = t[tx][j];
        __nv_bfloat16 h = __float2bfloat16(x);
        __nv_bfloat16 l = __float2bfloat16(x - __bfloat162float(h));
        size_t off = (size_t)(n0 + j) * HIDDEN + k0 + tx;
        H[off] = h;
        L[off] = l;
    }
}

// ============================================================================
// bf16x3 tensor-core GEMM via mma.sync (unchanged structure, 2 CTAs/SM)
// ============================================================================
#define GBK     32
#define TILE_B  10240        /* 128 * 80 bytes */
#define STAGE_B (4 * TILE_B) /* 40960 */

__global__ __launch_bounds__(256, 2) void gemm_mma_kernel(
    const __nv_bfloat16* __restrict__ Ah, const __nv_bfloat16* __restrict__ Al,
    const __nv_bfloat16* __restrict__ Bh, const __nv_bfloat16* __restrict__ Bl,
    float* __restrict__ C)
{
    extern __shared__ char smg[];
    const uint32_t sb = smem_u32(smg);
    const int tid  = threadIdx.x;
    const int wid  = tid >> 5;
    const int lane = tid & 31;
    const int wm = wid >> 2;
    const int wn = wid & 3;
    const int rowbase = blockIdx.y * 128;
    const int colbase = blockIdx.x * 128;

    const __nv_bfloat16* bases[4];
    bases[0] = Ah + (size_t)rowbase * HIDDEN;
    bases[1] = Al + (size_t)rowbase * HIDDEN;
    bases[2] = Bh + (size_t)colbase * HIDDEN;
    bases[3] = Bl + (size_t)colbase * HIDDEN;

    float acc[4][4][4];
    #pragma unroll
    for (int i = 0; i < 4; i++)
        #pragma unroll
        for (int j = 0; j < 4; j++)
            #pragma unroll
            for (int q = 0; q < 4; q++) acc[i][j][q] = 0.0f;

    const int NCH = HIDDEN / GBK;

    {
        #pragma unroll
        for (int it = 0; it < 8; it++) {
            int t = tid + it * 256;
            int tile = t >> 9;
            int r    = (t >> 2) & 127;
            int ch   = t & 3;
            const void* g = bases[tile] + (size_t)r * HIDDEN + ch * 8;
            uint32_t d = sb + tile * TILE_B + r * 80 + ch * 16;
            cp_async16(d, g);
        }
        CP_COMMIT();
    }

    for (int c = 0; c < NCH; c++) {
        const int p = c & 1;
        if (c + 1 < NCH) {
            const int kb = (c + 1) * GBK;
            #pragma unroll
            for (int it = 0; it < 8; it++) {
                int t = tid + it * 256;
                int tile = t >> 9;
                int r    = (t >> 2) & 127;
                int ch   = t & 3;
                const void* g = bases[tile] + (size_t)r * HIDDEN + kb + ch * 8;
                uint32_t d = sb + (p ^ 1) * STAGE_B + tile * TILE_B + r * 80 + ch * 16;
                cp_async16(d, g);
            }
            CP_COMMIT();
            CP_WAIT(1);
        } else {
            CP_WAIT(0);
        }
        __syncthreads();

        const uint32_t At_h = sb + p * STAGE_B;
        const uint32_t At_l = At_h + TILE_B;
        const uint32_t Bt_h = At_h + 2 * TILE_B;
        const uint32_t Bt_l = At_h + 3 * TILE_B;

        const int arow = lane & 15;
        const int aoff = ((lane >> 4) & 1) * 16;
        const int brow = (lane & 7) + ((lane >> 4) & 1) * 8;
        const int boff = ((lane >> 3) & 1) * 16;

        #pragma unroll
        for (int ks = 0; ks < 2; ks++) {
            const int kbyte = ks * 32;
            uint32_t ah[4][4], al[4][4];
            #pragma unroll
            for (int mi = 0; mi < 4; mi++) {
                uint32_t addr = At_h + (wm * 64 + mi * 16 + arow) * 80 + kbyte + aoff;
                ldsm_x4(ah[mi][0], ah[mi][1], ah[mi][2], ah[mi][3], addr);
            }
            #pragma unroll
            for (int mi = 0; mi < 4; mi++) {
                uint32_t addr = At_l + (wm * 64 + mi * 16 + arow) * 80 + kbyte + aoff;
                ldsm_x4(al[mi][0], al[mi][1], al[mi][2], al[mi][3], addr);
            }
            uint32_t bh[4][2], bl[4][2];
            #pragma unroll
            for (int nf2 = 0; nf2 < 2; nf2++) {
                uint32_t r0, r1, r2, r3;
                uint32_t addr = Bt_h + (wn * 32 + nf2 * 16 + brow) * 80 + kbyte + boff;
                ldsm_x4(r0, r1, r2, r3, addr);
                bh[nf2 * 2][0] = r0; bh[nf2 * 2][1] = r1;
                bh[nf2 * 2 + 1][0] = r2; bh[nf2 * 2 + 1][1] = r3;
                addr = Bt_l + (wn * 32 + nf2 * 16 + brow) * 80 + kbyte + boff;
                ldsm_x4(r0, r1, r2, r3, addr);
                bl[nf2 * 2][0] = r0; bl[nf2 * 2][1] = r1;
                bl[nf2 * 2 + 1][0] = r2; bl[nf2 * 2 + 1][1] = r3;
            }
            #pragma unroll
            for (int mi = 0; mi < 4; mi++)
                #pragma unroll
                for (int nf = 0; nf < 4; nf++) {
                    mma_bf16(acc[mi][nf], ah[mi][0], ah[mi][1], ah[mi][2], ah[mi][3],
                             bh[nf][0], bh[nf][1]);
                    mma_bf16(acc[mi][nf], ah[mi][0], ah[mi][1], ah[mi][2], ah[mi][3],
                             bl[nf][0], bl[nf][1]);
                    mma_bf16(acc[mi][nf], al[mi][0], al[mi][1], al[mi][2], al[mi][3],
                             bh[nf][0], bh[nf][1]);
                }
        }
        __syncthreads();
    }

    const int g = lane >> 2;
    const int t = lane & 3;
    #pragma unroll
    for (int mi = 0; mi < 4; mi++) {
        #pragma unroll
        for (int nf = 0; nf < 4; nf++) {
            float* base = C + (size_t)(rowbase + wm * 64 + mi * 16 + g) * HIDDEN
                            + colbase + wn * 32 + nf * 8 + t * 2;
            *(float2*)base = make_float2(acc[mi][nf][0], acc[mi][nf][1]);
            *(float2*)(base + (size_t)8 * HIDDEN) = make_float2(acc[mi][nf][2], acc[mi][nf][3]);
        }
    }
}

// ============================================================================
// RoPE + split: fp32 Q,K -> bf16 hi/lo (Q pre-scaled by 1/16)
// One thread per pair of channels. 32768 blocks x 256.
// ============================================================================
__global__ __launch_bounds__(256) void rope_split_kernel(
    const float* __restrict__ Qf, const float* __restrict__ Kf,
    const int* __restrict__ pos_ids,
    __nv_bfloat16* __restrict__ Qh, __nv_bfloat16* __restrict__ Ql,
    __nv_bfloat16* __restrict__ Kh, __nv_bfloat16* __restrict__ Kl)
{
    int idx = blockIdx.x * 256 + threadIdx.x;   // tok*16*128 + h*128 + j
    int j   = idx & 127;
    int h   = (idx >> 7) & 15;
    int tok = idx >> 11;                        // 0..4095
    int b   = tok >> 11;
    int s   = tok & 2047;

    size_t base = (size_t)tok * HIDDEN + h * 256 + 2 * j;
    float q0 = Qf[base], q1 = Qf[base + 1];
    float k0 = Kf[base], k1 = Kf[base + 1];

    if (j < 32) {
        int pos = pos_ids[b * SEQ + s];
        double inv = exp(-9.210340371976184 * (double)j / 32.0);
        float ang = (float)((double)pos * inv);
        float sv = sinf(ang), cv = cosf(ang);
        float t0 = q0 * cv - q1 * sv;
        float t1 = q1 * cv + q0 * sv;
        q0 = t0; q1 = t1;
        t0 = k0 * cv - k1 * sv;
        t1 = k1 * cv + k0 * sv;
        k0 = t0; k1 = t1;
    }
    q0 *= 0.0625f; q1 *= 0.0625f;   // 1/sqrt(256)

    __nv_bfloat16 qh0 = __float2bfloat16(q0), qh1 = __float2bfloat16(q1);
    __nv_bfloat16 kh0 = __float2bfloat16(k0), kh1 = __float2bfloat16(k1);
    float ql0 = q0 - __bfloat162float(qh0), ql1 = q1 - __bfloat162float(qh1);
    float kl0 = k0 - __bfloat162float(kh0), kl1 = k1 - __bfloat162float(kh1);

    *(uint32_t*)(Qh + base) = pack_bf16(__bfloat162float(qh0), __bfloat162float(qh1));
    *(uint32_t*)(Ql + base) = pack_bf16(ql0, ql1);
    *(uint32_t*)(Kh + base) = pack_bf16(__bfloat162float(kh0), __bfloat162float(kh1));
    *(uint32_t*)(Kl + base) = pack_bf16(kl0, kl1);
}

// ============================================================================
// Tensor-core flash attention, bf16x3 throughout, fp32 accumulation.
// CTA: 64 q-rows x D=256 for one (head, batch). KV streamed in 64-chunks.
// 8 warps: QK phase (qg = w&3, kvhalf = w>>2); PV phase (qg = w&3, dhalf = w>>2).
// ============================================================================
#define AQ   64
#define AKV  64
#define QSTR 528    /* bytes per row: 256 bf16 + 8 pad */
#define PSTR 144    /* bytes per row: 64 bf16 + 8 pad  */

#define A_QH 0
#define A_QL 33792
#define A_KH 67584
#define A_KL 101376
#define A_VH 135168
#define A_VL 168960
#define A_PH 202752
#define A_PL 211968
#define A_ST 221184      /* stats region */
#define A_SMEM_TOTAL 223488

__global__ __launch_bounds__(256, 1) void attn_mma_kernel(
    const __nv_bfloat16* __restrict__ Qh_g, const __nv_bfloat16* __restrict__ Ql_g,
    const __nv_bfloat16* __restrict__ Kh_g, const __nv_bfloat16* __restrict__ Kl_g,
    const __nv_bfloat16* __restrict__ Vh_g, const __nv_bfloat16* __restrict__ Vl_g,
    const float* __restrict__ amask,
    __nv_bfloat16* __restrict__ Oh, __nv_bfloat16* __restrict__ Ol)
{
    extern __shared__ char sma[];
    const uint32_t sb = smem_u32(sma);
    float* pmax   = (float*)(sma + A_ST);          // [2][64]
    float* psum   = (float*)(sma + A_ST + 512);    // [2][64]
    float* mrow   = (float*)(sma + A_ST + 1024);   // [64]
    float* lrow   = (float*)(sma + A_ST + 1280);
    float* corr   = (float*)(sma + A_ST + 1536);
    float* mnew   = (float*)(sma + A_ST + 1792);
    float* amask_s= (float*)(sma + A_ST + 2048);

    const int tid  = threadIdx.x;
    const int wid  = tid >> 5;
    const int lane = tid & 31;
    const int qg   = wid & 3;       // q-group (16 rows)
    const int kvh  = wid >> 2;      // kv half for QK
    const int dh   = wid >> 2;      // d half for PV
    const int qt   = (int)gridDim.x - 1 - (int)blockIdx.x;   // long CTAs first
    const int h    = blockIdx.y;
    const int b    = blockIdx.z;
    const int q0   = qt * AQ;

    const int g = lane >> 2;
    const int t4 = lane & 3;
    const int arow = lane & 15;
    const int aoff = ((lane >> 4) & 1) * 16;
    const int brow = (lane & 7) + ((lane >> 4) & 1) * 8;
    const int boff = ((lane >> 3) & 1) * 16;
    // V trans-load lane pattern
    const int vrow = (lane & 7) + ((lane >> 3) & 1) * 8;
    const int vcoff = (lane >> 4) * 8;

    if (tid < 64) { mrow[tid] = -1e30f; lrow[tid] = 0.0f; }

    // ---- Q loads (join first K commit group) ----
    {
        const __nv_bfloat16* qh = Qh_g + (size_t)(b * SEQ + q0) * HIDDEN + h * 256;
        const __nv_bfloat16* ql = Ql_g + (size_t)(b * SEQ + q0) * HIDDEN + h * 256;
        #pragma unroll
        for (int it = 0; it < 8; it++) {
            int t = tid + it * 256;
            int r = t >> 5, c = t & 31;
            cp_async16(sb + A_QH + r * QSTR + c * 16, qh + (size_t)r * HIDDEN + c * 8);
            cp_async16(sb + A_QL + r * QSTR + c * 16, ql + (size_t)r * HIDDEN + c * 8);
        }
    }

    float o[16][4];
    #pragma unroll
    for (int i = 0; i < 16; i++)
        #pragma unroll
        for (int q = 0; q < 4; q++) o[i][q] = 0.0f;

    for (int kc = 0; kc <= qt; kc++) {
        const int k0 = kc * AKV;
        if (kc) __syncthreads();   // previous PV done; K/V/P reusable

        // K hi/lo -> group 0 (plus Q on first chunk)
        {
            const __nv_bfloat16* kh = Kh_g + (size_t)(b * SEQ + k0) * HIDDEN + h * 256;
            const __nv_bfloat16* kl = Kl_g + (size_t)(b * SEQ + k0) * HIDDEN + h * 256;
            #pragma unroll
            for (int it = 0; it < 8; it++) {
                int t = tid + it * 256;
                int r = t >> 5, c = t & 31;
                cp_async16(sb + A_KH + r * QSTR + c * 16, kh + (size_t)r * HIDDEN + c * 8);
                cp_async16(sb + A_KL + r * QSTR + c * 16, kl + (size_t)r * HIDDEN + c * 8);
            }
            CP_COMMIT();
        }
        // V hi/lo -> group 1
        {
            const __nv_bfloat16* vh = Vh_g + (size_t)(b * SEQ + k0) * HIDDEN + h * 256;
            const __nv_bfloat16* vl = Vl_g + (size_t)(b * SEQ + k0) * HIDDEN + h * 256;
            #pragma unroll
            for (int it = 0; it < 8; it++) {
                int t = tid + it * 256;
                int r = t >> 5, c = t & 31;
                cp_async16(sb + A_VH + r * QSTR + c * 16, vh + (size_t)r * HIDDEN + c * 8);
                cp_async16(sb + A_VL + r * QSTR + c * 16, vl + (size_t)r * HIDDEN + c * 8);
            }
            CP_COMMIT();
        }
        if (tid < 64) amask_s[tid] = amask[b * SEQ + k0 + tid];

        CP_WAIT(1);           // Q(+first) and K resident
        __syncthreads();

        // ---- S = Q K^T (m16 x n32 per warp), 3-way split ----
        float s[4][4];
        #pragma unroll
        for (int nt = 0; nt < 4; nt++)
            #pragma unroll
            for (int q = 0; q < 4; q++) s[nt][q] = 0.0f;

        #pragma unroll
        for (int ks = 0; ks < 16; ks++) {
            const int kb = ks * 32;
            uint32_t qah[4], qal[4];
            ldsm_x4(qah[0], qah[1], qah[2], qah[3],
                    sb + A_QH + (qg * 16 + arow) * QSTR + kb + aoff);
            ldsm_x4(qal[0], qal[1], qal[2], qal[3],
                    sb + A_QL + (qg * 16 + arow) * QSTR + kb + aoff);
            uint32_t kbh[4][2], kbl[4][2];
            #pragma unroll
            for (int n2 = 0; n2 < 2; n2++) {
                uint32_t r0, r1, r2, r3;
                ldsm_x4(r0, r1, r2, r3,
                        sb + A_KH + (kvh * 32 + n2 * 16 + brow) * QSTR + kb + boff);
                kbh[n2 * 2][0] = r0; kbh[n2 * 2][1] = r1;
                kbh[n2 * 2 + 1][0] = r2; kbh[n2 * 2 + 1][1] = r3;
                ldsm_x4(r0, r1, r2, r3,
                        sb + A_KL + (kvh * 32 + n2 * 16 + brow) * QSTR + kb + boff);
                kbl[n2 * 2][0] = r0; kbl[n2 * 2][1] = r1;
                kbl[n2 * 2 + 1][0] = r2; kbl[n2 * 2 + 1][1] = r3;
            }
            #pragma unroll
            for (int nt = 0; nt < 4; nt++) {
                mma_bf16(s[nt], qah[0], qah[1], qah[2], qah[3], kbh[nt][0], kbh[nt][1]);
                mma_bf16(s[nt], qah[0], qah[1], qah[2], qah[3], kbl[nt][0], kbl[nt][1]);
                mma_bf16(s[nt], qal[0], qal[1], qal[2], qal[3], kbh[nt][0], kbh[nt][1]);
            }
        }

        // ---- mask (causal + padding) ----
        const int rA = q0 + qg * 16 + g;
        const int rB = rA + 8;
        #pragma unroll
        for (int nt = 0; nt < 4; nt++) {
            int lc = kvh * 32 + nt * 8 + t4 * 2;
            int cg = k0 + lc;
            bool p0 = amask_s[lc] > 0.0f;
            bool p1 = amask_s[lc + 1] > 0.0f;
            if (cg > rA || !p0)     s[nt][0] = -1e30f;
            if (cg + 1 > rA || !p1) s[nt][1] = -1e30f;
            if (cg > rB || !p0)     s[nt][2] = -1e30f;
            if (cg + 1 > rB || !p1) s[nt][3] = -1e30f;
        }

        // ---- partial row max ----
        float mA = -1e30f, mB = -1e30f;
        #pragma unroll
        for (int nt = 0; nt < 4; nt++) {
            mA = fmaxf(mA, fmaxf(s[nt][0], s[nt][1]));
            mB = fmaxf(mB, fmaxf(s[nt][2], s[nt][3]));
        }
        mA = fmaxf(mA, __shfl_xor_sync(0xffffffffu, mA, 1));
        mA = fmaxf(mA, __shfl_xor_sync(0xffffffffu, mA, 2));
        mB = fmaxf(mB, __shfl_xor_sync(0xffffffffu, mB, 1));
        mB = fmaxf(mB, __shfl_xor_sync(0xffffffffu, mB, 2));
        if (t4 == 0) {
            pmax[kvh * 64 + qg * 16 + g] = mA;
            pmax[kvh * 64 + qg * 16 + g + 8] = mB;
        }
        __syncthreads();

        if (tid < 64) {
            float mo = mrow[tid];
            float pm = fmaxf(pmax[tid], pmax[64 + tid]);
            float mn = fmaxf(mo, pm);
            mnew[tid] = mn;
            corr[tid] = __expf(mo - mn);
            mrow[tid] = mn;
        }
        __syncthreads();

        // ---- exp, partial sums, write P hi/lo ----
        {
            float mnA = mnew[qg * 16 + g];
            float mnB = mnew[qg * 16 + g + 8];
            float sA = 0.0f, sB = 0.0f;
            #pragma unroll
            for (int nt = 0; nt < 4; nt++) {
                float p0 = __expf(s[nt][0] - mnA);
                float p1 = __expf(s[nt][1] - mnA);
                float p2 = __expf(s[nt][2] - mnB);
                float p3 = __expf(s[nt][3] - mnB);
                sA += p0 + p1;
                sB += p2 + p3;
                // split to hi/lo and store packed pairs
                __nv_bfloat16 h0 = __float2bfloat16(p0), h1 = __float2bfloat16(p1);
                __nv_bfloat16 h2 = __float2bfloat16(p2), h3 = __float2bfloat16(p3);
                float l0 = p0 - __bfloat162float(h0), l1 = p1 - __bfloat162float(h1);
                float l2 = p2 - __bfloat162float(h2), l3 = p3 - __bfloat162float(h3);
                uint32_t cb = (kvh * 32 + nt * 8 + t4 * 2) * 2;
                uint32_t adrA = (qg * 16 + g) * PSTR + cb;
                uint32_t adrB = (qg * 16 + g + 8) * PSTR + cb;
                *(uint32_t*)(sma + A_PH + adrA) = pack_bf16(__bfloat162float(h0), __bfloat162float(h1));
                *(uint32_t*)(sma + A_PH + adrB) = pack_bf16(__bfloat162float(h2), __bfloat162float(h3));
                *(uint32_t*)(sma + A_PL + adrA) = pack_bf16(l0, l1);
                *(uint32_t*)(sma + A_PL + adrB) = pack_bf16(l2, l3);
            }
            sA += __shfl_xor_sync(0xffffffffu, sA, 1);
            sA += __shfl_xor_sync(0xffffffffu, sA, 2);
            sB += __shfl_xor_sync(0xffffffffu, sB, 1);
            sB += __shfl_xor_sync(0xffffffffu, sB, 2);
            if (t4 == 0) {
                psum[kvh * 64 + qg * 16 + g] = sA;
                psum[kvh * 64 + qg * 16 + g + 8] = sB;
            }
        }
        CP_WAIT(0);          // V resident
        __syncthreads();

        if (tid < 64)
            lrow[tid] = lrow[tid] * corr[tid] + psum[tid] + psum[64 + tid];

        // ---- rescale O, then O += P V (3-way split) ----
        {
            float cA = corr[qg * 16 + g];
            float cB = corr[qg * 16 + g + 8];
            #pragma unroll
            for (int nt = 0; nt < 16; nt++) {
                o[nt][0] *= cA; o[nt][1] *= cA;
                o[nt][2] *= cB; o[nt][3] *= cB;
            }
        }
        #pragma unroll
        for (int ks = 0; ks < 4; ks++) {
            uint32_t pah[4], pal[4];
            ldsm_x4(pah[0], pah[1], pah[2], pah[3],
                    sb + A_PH + (qg * 16 + arow) * PSTR + ks * 32 + aoff);
            ldsm_x4(pal[0], pal[1], pal[2], pal[3],
                    sb + A_PL + (qg * 16 + arow) * PSTR + ks * 32 + aoff);
            #pragma unroll
            for (int np = 0; np < 8; np++) {
                int col = dh * 128 + np * 16 + vcoff;
                uint32_t vrowg = (ks * 16 + vrow) * QSTR + col * 2;
                uint32_t vh0, vh1, vh2, vh3, vl0, vl1, vl2, vl3;
                ldsm_x4_t(vh0, vh1, vh2, vh3, sb + A_VH + vrowg);
                ldsm_x4_t(vl0, vl1, vl2, vl3, sb + A_VL + vrowg);
                mma_bf16(o[np * 2], pah[0], pah[1], pah[2], pah[3], vh0, vh1);
                mma_bf16(o[np * 2], pah[0], pah[1], pah[2], pah[3], vl0, vl1);
                mma_bf16(o[np * 2], pal[0], pal[1], pal[2], pal[3], vh0, vh1);
                mma_bf16(o[np * 2 + 1], pah[0], pah[1], pah[2], pah[3], vh2, vh3);
                mma_bf16(o[np * 2 + 1], pah[0], pah[1], pah[2], pah[3], vl2, vl3);
                mma_bf16(o[np * 2 + 1], pal[0], pal[1], pal[2], pal[3], vh2, vh3);
            }
        }
    }

    __syncthreads();   // lrow final
    {
        float invA = 1.0f / lrow[qg * 16 + g];
        float invB = 1.0f / lrow[qg * 16 + g + 8];
        size_t rowA = (size_t)(b * SEQ + q0 + qg * 16 + g) * HIDDEN;
        size_t rowB = rowA + (size_t)8 * HIDDEN;
        int colbase = h * 256 + dh * 128 + t4 * 2;
        #pragma unroll
        for (int nt = 0; nt < 16; nt++) {
            int col = colbase + nt * 8;
            float a0 = o[nt][0] * invA, a1 = o[nt][1] * invA;
            float b0 = o[nt][2] * invB, b1 = o[nt][3] * invB;
            __nv_bfloat16 ha0 = __float2bfloat16(a0), ha1 = __float2bfloat16(a1);
            __nv_bfloat16 hb0 = __float2bfloat16(b0), hb1 = __float2bfloat16(b1);
            *(uint32_t*)(Oh + rowA + col) = pack_bf16(__bfloat162float(ha0), __bfloat162float(ha1));
            *(uint32_t*)(Ol + rowA + col) = pack_bf16(a0 - __bfloat162float(ha0), a1 - __bfloat162float(ha1));
            *(uint32_t*)(Oh + rowB + col) = pack_bf16(__bfloat162float(hb0), __bfloat162float(hb1));
            *(uint32_t*)(Ol + rowB + col) = pack_bf16(b0 - __bfloat162float(hb0), b1 - __bfloat162float(hb1));
        }
    }
}

// ============================================================================
// Launch
// ============================================================================
extern "C" void kernel_launch(void* const* d_in, const int* in_sizes, int n_in,
                              void* d_out, int out_size)
{
    const float* X   = (const float*)d_in[0];
    const float* msk = (const float*)d_in[1];
    const int*   pos = (const int*)  d_in[2];
    const float* Wq  = (const float*)d_in[3];
    const float* Wk  = (const float*)d_in[4];
    const float* Wv  = (const float*)d_in[5];
    const float* Wo  = (const float*)d_in[6];
    float* out = (float*)d_out;

    float* f32 = nullptr;
    __nv_bfloat16* bf = nullptr;
    cudaGetSymbolAddress((void**)&f32, g_f32);
    cudaGetSymbolAddress((void**)&bf, g_bf16);

    float* Qb = f32;
    float* Kb = f32 + 1 * SLOT;
    float* Vb = f32 + 2 * SLOT;

    __nv_bfloat16* Xh  = bf + 0 * SLOT;
    __nv_bfloat16* Xl  = bf + 1 * SLOT;
    __nv_bfloat16* Oh  = bf + 2 * SLOT;
    __nv_bfloat16* Ol  = bf + 3 * SLOT;
    __nv_bfloat16* Wqh = bf + 4 * SLOT;  __nv_bfloat16* Wql = bf + 5 * SLOT;
    __nv_bfloat16* Wkh = bf + 6 * SLOT;  __nv_bfloat16* Wkl = bf + 7 * SLOT;
    __nv_bfloat16* Wvh = bf + 8 * SLOT;  __nv_bfloat16* Wvl = bf + 9 * SLOT;
    __nv_bfloat16* Woh = bf + 10 * SLOT; __nv_bfloat16* Wol = bf + 11 * SLOT;
    __nv_bfloat16* Qh  = bf + 12 * SLOT; __nv_bfloat16* Ql  = bf + 13 * SLOT;
    __nv_bfloat16* Kh  = bf + 14 * SLOT; __nv_bfloat16* Kl  = bf + 15 * SLOT;
    __nv_bfloat16* Vh  = bf + 16 * SLOT; __nv_bfloat16* Vl  = bf + 17 * SLOT;

    int split_blocks = (int)(SLOT / (256 * 4));
    split_rows_kernel<<<split_blocks, 256>>>(X, Xh, Xl);
    dim3 tgrid(HIDDEN / 32, HIDDEN / 32);
    split_T_kernel<<<tgrid, 256>>>(Wq, Wqh, Wql);
    split_T_kernel<<<tgrid, 256>>>(Wk, Wkh, Wkl);
    split_T_kernel<<<tgrid, 256>>>(Wv, Wvh, Wvl);
    split_T_kernel<<<tgrid, 256>>>(Wo, Woh, Wol);

    int gsmem = 2 * STAGE_B;   // 81920
    cudaFuncSetAttribute(gemm_mma_kernel,
                         cudaFuncAttributeMaxDynamicSharedMemorySize, gsmem);
    dim3 ggrid(HIDDEN / 128, MROWS / 128);
    gemm_mma_kernel<<<ggrid, 256, gsmem>>>(Xh, Xl, Wqh, Wql, Qb);
    gemm_mma_kernel<<<ggrid, 256, gsmem>>>(Xh, Xl, Wkh, Wkl, Kb);
    gemm_mma_kernel<<<ggrid, 256, gsmem>>>(Xh, Xl, Wvh, Wvl, Vb);

    // RoPE + bf16 split for Q/K; plain split for V
    rope_split_kernel<<<32768, 256>>>(Qb, Kb, pos, Qh, Ql, Kh, Kl);
    split_rows_kernel<<<split_blocks, 256>>>(Vb, Vh, Vl);

    cudaFuncSetAttribute(attn_mma_kernel,
                         cudaFuncAttributeMaxDynamicSharedMemorySize, A_SMEM_TOTAL);
    dim3 agrid(SEQ / AQ, NHEADS, BATCH);   // (32, 16, 2)
    attn_mma_kernel<<<agrid, 256, A_SMEM_TOTAL>>>(Qh, Ql, Kh, Kl, Vh, Vl, msk, Oh, Ol);

    gemm_mma_kernel<<<ggrid, 256, gsmem>>>(Oh, Ol, Woh, Wol, out);
}

// round 5
// speedup vs baseline: 3.7975x; 1.0155x over previous
#include <cuda_runtime.h>
#include <cuda_bf16.h>
#include <math.h>
#include <stdint.h>

#define HIDDEN 4096
#define NHEADS 16
#define HDIM   256
#define ROT    64
#define BATCH  2
#define SEQ    2048
#define MROWS  (BATCH*SEQ)   /* 4096 */

// bf16 scratch slots (each 4096*4096 = 32 MB):
//  0:Xh 1:Xl 2:Oh 3:Ol
//  4-6:  Wqkv_h (stacked [Wq;Wk;Wv], 12288 x 4096)
//  7-9:  Wqkv_l
//  10:Wo_h 11:Wo_l
//  12:Qh 13:Ql 14:Kh 15:Kl 16:Vh 17:Vl
__device__ __nv_bfloat16 g_bf16[18ull * MROWS * HIDDEN];

#define SLOT ((size_t)MROWS * HIDDEN)

// ============================================================================
// PTX helpers (arch-neutral sm_80/sm_90 features — harness builds via
// virtual arch compute_103, no tcgen05/'a'-suffix features)
// ============================================================================
__device__ __forceinline__ uint32_t smem_u32(const void* p) {
    uint32_t a;
    asm("{ .reg .u64 t; cvta.to.shared.u64 t, %1; cvt.u32.u64 %0, t; }"
        : "=r"(a) : "l"(p));
    return a;
}

__device__ __forceinline__ void cp_async16(uint32_t dst, const void* src) {
    asm volatile("cp.async.cg.shared.global [%0], [%1], 16;"
                 :: "r"(dst), "l"(src));
}
#define CP_COMMIT() asm volatile("cp.async.commit_group;" ::: "memory")
#define CP_WAIT(n)  asm volatile("cp.async.wait_group %0;" :: "n"(n) : "memory")

__device__ __forceinline__ void ldsm_x4(uint32_t& r0, uint32_t& r1,
                                        uint32_t& r2, uint32_t& r3,
                                        uint32_t addr) {
    asm volatile("ldmatrix.sync.aligned.m8n8.x4.shared.b16 {%0,%1,%2,%3}, [%4];"
                 : "=r"(r0), "=r"(r1), "=r"(r2), "=r"(r3) : "r"(addr));
}
__device__ __forceinline__ void ldsm_x4_t(uint32_t& r0, uint32_t& r1,
                                          uint32_t& r2, uint32_t& r3,
                                          uint32_t addr) {
    asm volatile("ldmatrix.sync.aligned.m8n8.x4.trans.shared.b16 {%0,%1,%2,%3}, [%4];"
                 : "=r"(r0), "=r"(r1), "=r"(r2), "=r"(r3) : "r"(addr));
}

__device__ __forceinline__ void mma_bf16(float c[4],
                                         uint32_t a0, uint32_t a1,
                                         uint32_t a2, uint32_t a3,
                                         uint32_t b0, uint32_t b1) {
    asm volatile(
        "mma.sync.aligned.m16n8k16.row.col.f32.bf16.bf16.f32 "
        "{%0,%1,%2,%3}, {%4,%5,%6,%7}, {%8,%9}, {%0,%1,%2,%3};"
        : "+f"(c[0]), "+f"(c[1]), "+f"(c[2]), "+f"(c[3])
        : "r"(a0), "r"(a1), "r"(a2), "r"(a3), "r"(b0), "r"(b1));
}

__device__ __forceinline__ uint32_t pack_bf16(float a, float b) {
    __nv_bfloat162 t = __floats2bfloat162_rn(a, b);
    return *(uint32_t*)&t;
}

// ============================================================================
// Split kernels: fp32 -> (hi, lo) bf16
// ============================================================================
__global__ __launch_bounds__(256) void split_rows_kernel(
    const float* __restrict__ X, __nv_bfloat16* __restrict__ H,
    __nv_bfloat16* __restrict__ L)
{
    size_t i = ((size_t)blockIdx.x * 256 + threadIdx.x) * 4;
    float4 v = *(const float4*)(X + i);
    float f[4] = {v.x, v.y, v.z, v.w};
    __nv_bfloat16 hh[4], ll[4];
    #pragma unroll
    for (int j = 0; j < 4; j++) {
        hh[j] = __float2bfloat16(f[j]);
        ll[j] = __float2bfloat16(f[j] - __bfloat162float(hh[j]));
    }
    *(uint2*)(H + i) = *(uint2*)hh;
    *(uint2*)(L + i) = *(uint2*)ll;
}

// Transpose + split: W fp32 [K,N] row-major -> H/L bf16 [N,K] row-major
__global__ __launch_bounds__(256) void split_T_kernel(
    const float* __restrict__ W, __nv_bfloat16* __restrict__ H,
    __nv_bfloat16* __restrict__ L)
{
    __shared__ float t[32][33];
    const int n0 = blockIdx.x * 32;
    const int k0 = blockIdx.y * 32;
    const int tx = threadIdx.x & 31;
    const int ty = threadIdx.x >> 5;
    #pragma unroll
    for (int j = ty; j < 32; j += 8)
        t[j][tx] = W[(size_t)(k0 + j) * HIDDEN + n0 + tx];
    __syncthreads();
    #pragma unroll
    for (int j = ty; j < 32; j += 8) {
        float x = t[tx][j];
        __nv_bfloat16 h = __float2bfloat16(x);
        __nv_bfloat16 l = __float2bfloat16(x - __bfloat162float(h));
        size_t off = (size_t)(n0 + j) * HIDDEN + k0 + tx;
        H[off] = h;
        L[off] = l;
    }
}

// ============================================================================
// Shared GEMM mainloop macro-free core (BM=BN=128, BK=32, 8 warps, 2 CTA/SM)
// ============================================================================
#define GBK     32
#define TILE_B  10240        /* 128 * 80 bytes */
#define STAGE_B (4 * TILE_B) /* 40960 */

// ---------------------------------------------------------------------------
// Fused QKV projection GEMM: A = X (hi/lo) [4096 x 4096],
// B = Wqkv (hi/lo) [12288 x 4096] row-major (pre-transposed).
// Epilogue by region: 0=Q (rope + 1/16 scale + split), 1=K (rope + split),
// 2=V (split only). Writes bf16 hi/lo in [MROWS, HIDDEN] layout.
// ---------------------------------------------------------------------------
__global__ __launch_bounds__(256, 2) void gemm_qkv_kernel(
    const __nv_bfloat16* __restrict__ Ah, const __nv_bfloat16* __restrict__ Al,
    const __nv_bfloat16* __restrict__ Bh, const __nv_bfloat16* __restrict__ Bl,
    const int* __restrict__ pos_ids,
    __nv_bfloat16* __restrict__ Qh, __nv_bfloat16* __restrict__ Ql,
    __nv_bfloat16* __restrict__ Kh, __nv_bfloat16* __restrict__ Kl,
    __nv_bfloat16* __restrict__ Vh, __nv_bfloat16* __restrict__ Vl)
{
    extern __shared__ char smg[];
    const uint32_t sb = smem_u32(smg);
    const int tid  = threadIdx.x;
    const int wid  = tid >> 5;
    const int lane = tid & 31;
    const int wm = wid >> 2;
    const int wn = wid & 3;
    const int rowbase = blockIdx.y * 128;
    const int colbase = blockIdx.x * 128;   // 0..12160

    const __nv_bfloat16* bases[4];
    bases[0] = Ah + (size_t)rowbase * HIDDEN;
    bases[1] = Al + (size_t)rowbase * HIDDEN;
    bases[2] = Bh + (size_t)colbase * HIDDEN;
    bases[3] = Bl + (size_t)colbase * HIDDEN;

    float acc[4][4][4];
    #pragma unroll
    for (int i = 0; i < 4; i++)
        #pragma unroll
        for (int j = 0; j < 4; j++)
            #pragma unroll
            for (int q = 0; q < 4; q++) acc[i][j][q] = 0.0f;

    const int NCH = HIDDEN / GBK;

    {
        #pragma unroll
        for (int it = 0; it < 8; it++) {
            int t = tid + it * 256;
            int tile = t >> 9;
            int r    = (t >> 2) & 127;
            int ch   = t & 3;
            const void* g = bases[tile] + (size_t)r * HIDDEN + ch * 8;
            uint32_t d = sb + tile * TILE_B + r * 80 + ch * 16;
            cp_async16(d, g);
        }
        CP_COMMIT();
    }

    for (int c = 0; c < NCH; c++) {
        const int p = c & 1;
        if (c + 1 < NCH) {
            const int kb = (c + 1) * GBK;
            #pragma unroll
            for (int it = 0; it < 8; it++) {
                int t = tid + it * 256;
                int tile = t >> 9;
                int r    = (t >> 2) & 127;
                int ch   = t & 3;
                const void* g = bases[tile] + (size_t)r * HIDDEN + kb + ch * 8;
                uint32_t d = sb + (p ^ 1) * STAGE_B + tile * TILE_B + r * 80 + ch * 16;
                cp_async16(d, g);
            }
            CP_COMMIT();
            CP_WAIT(1);
        } else {
            CP_WAIT(0);
        }
        __syncthreads();

        const uint32_t At_h = sb + p * STAGE_B;
        const uint32_t At_l = At_h + TILE_B;
        const uint32_t Bt_h = At_h + 2 * TILE_B;
        const uint32_t Bt_l = At_h + 3 * TILE_B;

        const int arow = lane & 15;
        const int aoff = ((lane >> 4) & 1) * 16;
        const int brow = (lane & 7) + ((lane >> 4) & 1) * 8;
        const int boff = ((lane >> 3) & 1) * 16;

        #pragma unroll
        for (int ks = 0; ks < 2; ks++) {
            const int kbyte = ks * 32;
            uint32_t ah[4][4], al[4][4];
            #pragma unroll
            for (int mi = 0; mi < 4; mi++) {
                uint32_t addr = At_h + (wm * 64 + mi * 16 + arow) * 80 + kbyte + aoff;
                ldsm_x4(ah[mi][0], ah[mi][1], ah[mi][2], ah[mi][3], addr);
            }
            #pragma unroll
            for (int mi = 0; mi < 4; mi++) {
                uint32_t addr = At_l + (wm * 64 + mi * 16 + arow) * 80 + kbyte + aoff;
                ldsm_x4(al[mi][0], al[mi][1], al[mi][2], al[mi][3], addr);
            }
            uint32_t bh[4][2], bl[4][2];
            #pragma unroll
            for (int nf2 = 0; nf2 < 2; nf2++) {
                uint32_t r0, r1, r2, r3;
                uint32_t addr = Bt_h + (wn * 32 + nf2 * 16 + brow) * 80 + kbyte + boff;
                ldsm_x4(r0, r1, r2, r3, addr);
                bh[nf2 * 2][0] = r0; bh[nf2 * 2][1] = r1;
                bh[nf2 * 2 + 1][0] = r2; bh[nf2 * 2 + 1][1] = r3;
                addr = Bt_l + (wn * 32 + nf2 * 16 + brow) * 80 + kbyte + boff;
                ldsm_x4(r0, r1, r2, r3, addr);
                bl[nf2 * 2][0] = r0; bl[nf2 * 2][1] = r1;
                bl[nf2 * 2 + 1][0] = r2; bl[nf2 * 2 + 1][1] = r3;
            }
            #pragma unroll
            for (int mi = 0; mi < 4; mi++)
                #pragma unroll
                for (int nf = 0; nf < 4; nf++) {
                    mma_bf16(acc[mi][nf], ah[mi][0], ah[mi][1], ah[mi][2], ah[mi][3],
                             bh[nf][0], bh[nf][1]);
                    mma_bf16(acc[mi][nf], ah[mi][0], ah[mi][1], ah[mi][2], ah[mi][3],
                             bl[nf][0], bl[nf][1]);
                    mma_bf16(acc[mi][nf], al[mi][0], al[mi][1], al[mi][2], al[mi][3],
                             bh[nf][0], bh[nf][1]);
                }
        }
        __syncthreads();
    }

    // ---- fused epilogue ----
    const int region = colbase >> 12;   // 0=Q, 1=K, 2=V
    __nv_bfloat16 *H, *L;
    if (region == 0)      { H = Qh; L = Ql; }
    else if (region == 1) { H = Kh; L = Kl; }
    else                  { H = Vh; L = Vl; }
    const int ncolbase = colbase & 4095;

    const int g = lane >> 2;
    const int t4 = lane & 3;
    // rotary applies when the head-relative column < 64: heads are 256-wide
    // and colbase is a multiple of 128, so only (colbase&255)==0 && wn<2.
    const bool rotwarp = (region < 2) && ((colbase & 255) == 0) && (wn < 2);

    double invd[4];
    if (rotwarp) {
        #pragma unroll
        for (int nf = 0; nf < 4; nf++) {
            int j = wn * 16 + nf * 4 + t4;   // pair index 0..31
            invd[nf] = exp(-9.210340371976184 * (double)j / 32.0);
        }
    }
    const float qscale = (region == 0) ? 0.0625f : 1.0f;

    #pragma unroll
    for (int mi = 0; mi < 4; mi++) {
        const int rA = rowbase + wm * 64 + mi * 16 + g;
        const int rB = rA + 8;
        int posA = 0, posB = 0;
        if (rotwarp) { posA = pos_ids[rA]; posB = pos_ids[rB]; }
        #pragma unroll
        for (int nf = 0; nf < 4; nf++) {
            float v0 = acc[mi][nf][0], v1 = acc[mi][nf][1];
            float v2 = acc[mi][nf][2], v3 = acc[mi][nf][3];
            if (rotwarp) {
                float angA = (float)((double)posA * invd[nf]);
                float angB = (float)((double)posB * invd[nf]);
                float sA = sinf(angA), cA = cosf(angA);
                float sB = sinf(angB), cB = cosf(angB);
                float t0 = v0 * cA - v1 * sA;
                float t1 = v1 * cA + v0 * sA;
                v0 = t0; v1 = t1;
                t0 = v2 * cB - v3 * sB;
                t1 = v3 * cB + v2 * sB;
                v2 = t0; v3 = t1;
            }
            v0 *= qscale; v1 *= qscale; v2 *= qscale; v3 *= qscale;

            __nv_bfloat16 h0 = __float2bfloat16(v0), h1 = __float2bfloat16(v1);
            __nv_bfloat16 h2 = __float2bfloat16(v2), h3 = __float2bfloat16(v3);
            float l0 = v0 - __bfloat162float(h0), l1 = v1 - __bfloat162float(h1);
            float l2 = v2 - __bfloat162float(h2), l3 = v3 - __bfloat162float(h3);

            size_t ncol = (size_t)(ncolbase + wn * 32 + nf * 8 + t4 * 2);
            size_t offA = (size_t)rA * HIDDEN + ncol;
            size_t offB = (size_t)rB * HIDDEN + ncol;
            *(uint32_t*)(H + offA) = pack_bf16(__bfloat162float(h0), __bfloat162float(h1));
            *(uint32_t*)(L + offA) = pack_bf16(l0, l1);
            *(uint32_t*)(H + offB) = pack_bf16(__bfloat162float(h2), __bfloat162float(h3));
            *(uint32_t*)(L + offB) = pack_bf16(l2, l3);
        }
    }
}

// ---------------------------------------------------------------------------
// Output projection GEMM (plain fp32 epilogue)
// ---------------------------------------------------------------------------
__global__ __launch_bounds__(256, 2) void gemm_mma_kernel(
    const __nv_bfloat16* __restrict__ Ah, const __nv_bfloat16* __restrict__ Al,
    const __nv_bfloat16* __restrict__ Bh, const __nv_bfloat16* __restrict__ Bl,
    float* __restrict__ C)
{
    extern __shared__ char smg[];
    const uint32_t sb = smem_u32(smg);
    const int tid  = threadIdx.x;
    const int wid  = tid >> 5;
    const int lane = tid & 31;
    const int wm = wid >> 2;
    const int wn = wid & 3;
    const int rowbase = blockIdx.y * 128;
    const int colbase = blockIdx.x * 128;

    const __nv_bfloat16* bases[4];
    bases[0] = Ah + (size_t)rowbase * HIDDEN;
    bases[1] = Al + (size_t)rowbase * HIDDEN;
    bases[2] = Bh + (size_t)colbase * HIDDEN;
    bases[3] = Bl + (size_t)colbase * HIDDEN;

    float acc[4][4][4];
    #pragma unroll
    for (int i = 0; i < 4; i++)
        #pragma unroll
        for (int j = 0; j < 4; j++)
            #pragma unroll
            for (int q = 0; q < 4; q++) acc[i][j][q] = 0.0f;

    const int NCH = HIDDEN / GBK;

    {
        #pragma unroll
        for (int it = 0; it < 8; it++) {
            int t = tid + it * 256;
            int tile = t >> 9;
            int r    = (t >> 2) & 127;
            int ch   = t & 3;
            const void* g = bases[tile] + (size_t)r * HIDDEN + ch * 8;
            uint32_t d = sb + tile * TILE_B + r * 80 + ch * 16;
            cp_async16(d, g);
        }
        CP_COMMIT();
    }

    for (int c = 0; c < NCH; c++) {
        const int p = c & 1;
        if (c + 1 < NCH) {
            const int kb = (c + 1) * GBK;
            #pragma unroll
            for (int it = 0; it < 8; it++) {
                int t = tid + it * 256;
                int tile = t >> 9;
                int r    = (t >> 2) & 127;
                int ch   = t & 3;
                const void* g = bases[tile] + (size_t)r * HIDDEN + kb + ch * 8;
                uint32_t d = sb + (p ^ 1) * STAGE_B + tile * TILE_B + r * 80 + ch * 16;
                cp_async16(d, g);
            }
            CP_COMMIT();
            CP_WAIT(1);
        } else {
            CP_WAIT(0);
        }
        __syncthreads();

        const uint32_t At_h = sb + p * STAGE_B;
        const uint32_t At_l = At_h + TILE_B;
        const uint32_t Bt_h = At_h + 2 * TILE_B;
        const uint32_t Bt_l = At_h + 3 * TILE_B;

        const int arow = lane & 15;
        const int aoff = ((lane >> 4) & 1) * 16;
        const int brow = (lane & 7) + ((lane >> 4) & 1) * 8;
        const int boff = ((lane >> 3) & 1) * 16;

        #pragma unroll
        for (int ks = 0; ks < 2; ks++) {
            const int kbyte = ks * 32;
            uint32_t ah[4][4], al[4][4];
            #pragma unroll
            for (int mi = 0; mi < 4; mi++) {
                uint32_t addr = At_h + (wm * 64 + mi * 16 + arow) * 80 + kbyte + aoff;
                ldsm_x4(ah[mi][0], ah[mi][1], ah[mi][2], ah[mi][3], addr);
            }
            #pragma unroll
            for (int mi = 0; mi < 4; mi++) {
                uint32_t addr = At_l + (wm * 64 + mi * 16 + arow) * 80 + kbyte + aoff;
                ldsm_x4(al[mi][0], al[mi][1], al[mi][2], al[mi][3], addr);
            }
            uint32_t bh[4][2], bl[4][2];
            #pragma unroll
            for (int nf2 = 0; nf2 < 2; nf2++) {
                uint32_t r0, r1, r2, r3;
                uint32_t addr = Bt_h + (wn * 32 + nf2 * 16 + brow) * 80 + kbyte + boff;
                ldsm_x4(r0, r1, r2, r3, addr);
                bh[nf2 * 2][0] = r0; bh[nf2 * 2][1] = r1;
                bh[nf2 * 2 + 1][0] = r2; bh[nf2 * 2 + 1][1] = r3;
                addr = Bt_l + (wn * 32 + nf2 * 16 + brow) * 80 + kbyte + boff;
                ldsm_x4(r0, r1, r2, r3, addr);
                bl[nf2 * 2][0] = r0; bl[nf2 * 2][1] = r1;
                bl[nf2 * 2 + 1][0] = r2; bl[nf2 * 2 + 1][1] = r3;
            }
            #pragma unroll
            for (int mi = 0; mi < 4; mi++)
                #pragma unroll
                for (int nf = 0; nf < 4; nf++) {
                    mma_bf16(acc[mi][nf], ah[mi][0], ah[mi][1], ah[mi][2], ah[mi][3],
                             bh[nf][0], bh[nf][1]);
                    mma_bf16(acc[mi][nf], ah[mi][0], ah[mi][1], ah[mi][2], ah[mi][3],
                             bl[nf][0], bl[nf][1]);
                    mma_bf16(acc[mi][nf], al[mi][0], al[mi][1], al[mi][2], al[mi][3],
                             bh[nf][0], bh[nf][1]);
                }
        }
        __syncthreads();
    }

    const int g = lane >> 2;
    const int t = lane & 3;
    #pragma unroll
    for (int mi = 0; mi < 4; mi++) {
        #pragma unroll
        for (int nf = 0; nf < 4; nf++) {
            float* base = C + (size_t)(rowbase + wm * 64 + mi * 16 + g) * HIDDEN
                            + colbase + wn * 32 + nf * 8 + t * 2;
            *(float2*)base = make_float2(acc[mi][nf][0], acc[mi][nf][1]);
            *(float2*)(base + (size_t)8 * HIDDEN) = make_float2(acc[mi][nf][2], acc[mi][nf][3]);
        }
    }
}

// ============================================================================
// Tensor-core flash attention, bf16x3, fp32 accumulation. (unchanged from R4)
// ============================================================================
#define AQ   64
#define AKV  64
#define QSTR 528
#define PSTR 144

#define A_QH 0
#define A_QL 33792
#define A_KH 67584
#define A_KL 101376
#define A_VH 135168
#define A_VL 168960
#define A_PH 202752
#define A_PL 211968
#define A_ST 221184
#define A_SMEM_TOTAL 223488

__global__ __launch_bounds__(256, 1) void attn_mma_kernel(
    const __nv_bfloat16* __restrict__ Qh_g, const __nv_bfloat16* __restrict__ Ql_g,
    const __nv_bfloat16* __restrict__ Kh_g, const __nv_bfloat16* __restrict__ Kl_g,
    const __nv_bfloat16* __restrict__ Vh_g, const __nv_bfloat16* __restrict__ Vl_g,
    const float* __restrict__ amask,
    __nv_bfloat16* __restrict__ Oh, __nv_bfloat16* __restrict__ Ol)
{
    extern __shared__ char sma[];
    const uint32_t sb = smem_u32(sma);
    float* pmax   = (float*)(sma + A_ST);
    float* psum   = (float*)(sma + A_ST + 512);
    float* mrow   = (float*)(sma + A_ST + 1024);
    float* lrow   = (float*)(sma + A_ST + 1280);
    float* corr   = (float*)(sma + A_ST + 1536);
    float* mnew   = (float*)(sma + A_ST + 1792);
    float* amask_s= (float*)(sma + A_ST + 2048);

    const int tid  = threadIdx.x;
    const int wid  = tid >> 5;
    const int lane = tid & 31;
    const int qg   = wid & 3;
    const int kvh  = wid >> 2;
    const int dh   = wid >> 2;
    const int qt   = (int)gridDim.x - 1 - (int)blockIdx.x;
    const int h    = blockIdx.y;
    const int b    = blockIdx.z;
    const int q0   = qt * AQ;

    const int g = lane >> 2;
    const int t4 = lane & 3;
    const int arow = lane & 15;
    const int aoff = ((lane >> 4) & 1) * 16;
    const int brow = (lane & 7) + ((lane >> 4) & 1) * 8;
    const int boff = ((lane >> 3) & 1) * 16;
    const int vrow = (lane & 7) + ((lane >> 3) & 1) * 8;
    const int vcoff = (lane >> 4) * 8;

    if (tid < 64) { mrow[tid] = -1e30f; lrow[tid] = 0.0f; }

    {
        const __nv_bfloat16* qh = Qh_g + (size_t)(b * SEQ + q0) * HIDDEN + h * 256;
        const __nv_bfloat16* ql = Ql_g + (size_t)(b * SEQ + q0) * HIDDEN + h * 256;
        #pragma unroll
        for (int it = 0; it < 8; it++) {
            int t = tid + it * 256;
            int r = t >> 5, c = t & 31;
            cp_async16(sb + A_QH + r * QSTR + c * 16, qh + (size_t)r * HIDDEN + c * 8);
            cp_async16(sb + A_QL + r * QSTR + c * 16, ql + (size_t)r * HIDDEN + c * 8);
        }
    }

    float o[16][4];
    #pragma unroll
    for (int i = 0; i < 16; i++)
        #pragma unroll
        for (int q = 0; q < 4; q++) o[i][q] = 0.0f;

    for (int kc = 0; kc <= qt; kc++) {
        const int k0 = kc * AKV;
        if (kc) __syncthreads();

        {
            const __nv_bfloat16* kh = Kh_g + (size_t)(b * SEQ + k0) * HIDDEN + h * 256;
            const __nv_bfloat16* kl = Kl_g + (size_t)(b * SEQ + k0) * HIDDEN + h * 256;
            #pragma unroll
            for (int it = 0; it < 8; it++) {
                int t = tid + it * 256;
                int r = t >> 5, c = t & 31;
                cp_async16(sb + A_KH + r * QSTR + c * 16, kh + (size_t)r * HIDDEN + c * 8);
                cp_async16(sb + A_KL + r * QSTR + c * 16, kl + (size_t)r * HIDDEN + c * 8);
            }
            CP_COMMIT();
        }
        {
            const __nv_bfloat16* vh = Vh_g + (size_t)(b * SEQ + k0) * HIDDEN + h * 256;
            const __nv_bfloat16* vl = Vl_g + (size_t)(b * SEQ + k0) * HIDDEN + h * 256;
            #pragma unroll
            for (int it = 0; it < 8; it++) {
                int t = tid + it * 256;
                int r = t >> 5, c = t & 31;
                cp_async16(sb + A_VH + r * QSTR + c * 16, vh + (size_t)r * HIDDEN + c * 8);
                cp_async16(sb + A_VL + r * QSTR + c * 16, vl + (size_t)r * HIDDEN + c * 8);
            }
            CP_COMMIT();
        }
        if (tid < 64) amask_s[tid] = amask[b * SEQ + k0 + tid];

        CP_WAIT(1);
        __syncthreads();

        float s[4][4];
        #pragma unroll
        for (int nt = 0; nt < 4; nt++)
            #pragma unroll
            for (int q = 0; q < 4; q++) s[nt][q] = 0.0f;

        #pragma unroll
        for (int ks = 0; ks < 16; ks++) {
            const int kb = ks * 32;
            uint32_t qah[4], qal[4];
            ldsm_x4(qah[0], qah[1], qah[2], qah[3],
                    sb + A_QH + (qg * 16 + arow) * QSTR + kb + aoff);
            ldsm_x4(qal[0], qal[1], qal[2], qal[3],
                    sb + A_QL + (qg * 16 + arow) * QSTR + kb + aoff);
            uint32_t kbh[4][2], kbl[4][2];
            #pragma unroll
            for (int n2 = 0; n2 < 2; n2++) {
                uint32_t r0, r1, r2, r3;
                ldsm_x4(r0, r1, r2, r3,
                        sb + A_KH + (kvh * 32 + n2 * 16 + brow) * QSTR + kb + boff);
                kbh[n2 * 2][0] = r0; kbh[n2 * 2][1] = r1;
                kbh[n2 * 2 + 1][0] = r2; kbh[n2 * 2 + 1][1] = r3;
                ldsm_x4(r0, r1, r2, r3,
                        sb + A_KL + (kvh * 32 + n2 * 16 + brow) * QSTR + kb + boff);
                kbl[n2 * 2][0] = r0; kbl[n2 * 2][1] = r1;
                kbl[n2 * 2 + 1][0] = r2; kbl[n2 * 2 + 1][1] = r3;
            }
            #pragma unroll
            for (int nt = 0; nt < 4; nt++) {
                mma_bf16(s[nt], qah[0], qah[1], qah[2], qah[3], kbh[nt][0], kbh[nt][1]);
                mma_bf16(s[nt], qah[0], qah[1], qah[2], qah[3], kbl[nt][0], kbl[nt][1]);
                mma_bf16(s[nt], qal[0], qal[1], qal[2], qal[3], kbh[nt][0], kbh[nt][1]);
            }
        }

        const int rA = q0 + qg * 16 + g;
        const int rB = rA + 8;
        #pragma unroll
        for (int nt = 0; nt < 4; nt++) {
            int lc = kvh * 32 + nt * 8 + t4 * 2;
            int cg = k0 + lc;
            bool p0 = amask_s[lc] > 0.0f;
            bool p1 = amask_s[lc + 1] > 0.0f;
            if (cg > rA || !p0)     s[nt][0] = -1e30f;
            if (cg + 1 > rA || !p1) s[nt][1] = -1e30f;
            if (cg > rB || !p0)     s[nt][2] = -1e30f;
            if (cg + 1 > rB || !p1) s[nt][3] = -1e30f;
        }

        float mA = -1e30f, mB = -1e30f;
        #pragma unroll
        for (int nt = 0; nt < 4; nt++) {
            mA = fmaxf(mA, fmaxf(s[nt][0], s[nt][1]));
            mB = fmaxf(mB, fmaxf(s[nt][2], s[nt][3]));
        }
        mA = fmaxf(mA, __shfl_xor_sync(0xffffffffu, mA, 1));
        mA = fmaxf(mA, __shfl_xor_sync(0xffffffffu, mA, 2));
        mB = fmaxf(mB, __shfl_xor_sync(0xffffffffu, mB, 1));
        mB = fmaxf(mB, __shfl_xor_sync(0xffffffffu, mB, 2));
        if (t4 == 0) {
            pmax[kvh * 64 + qg * 16 + g] = mA;
            pmax[kvh * 64 + qg * 16 + g + 8] = mB;
        }
        __syncthreads();

        if (tid < 64) {
            float mo = mrow[tid];
            float pm = fmaxf(pmax[tid], pmax[64 + tid]);
            float mn = fmaxf(mo, pm);
            mnew[tid] = mn;
            corr[tid] = __expf(mo - mn);
            mrow[tid] = mn;
        }
        __syncthreads();

        {
            float mnA = mnew[qg * 16 + g];
            float mnB = mnew[qg * 16 + g + 8];
            float sA = 0.0f, sB = 0.0f;
            #pragma unroll
            for (int nt = 0; nt < 4; nt++) {
                float p0 = __expf(s[nt][0] - mnA);
                float p1 = __expf(s[nt][1] - mnA);
                float p2 = __expf(s[nt][2] - mnB);
                float p3 = __expf(s[nt][3] - mnB);
                sA += p0 + p1;
                sB += p2 + p3;
                __nv_bfloat16 h0 = __float2bfloat16(p0), h1 = __float2bfloat16(p1);
                __nv_bfloat16 h2 = __float2bfloat16(p2), h3 = __float2bfloat16(p3);
                float l0 = p0 - __bfloat162float(h0), l1 = p1 - __bfloat162float(h1);
                float l2 = p2 - __bfloat162float(h2), l3 = p3 - __bfloat162float(h3);
                uint32_t cb = (kvh * 32 + nt * 8 + t4 * 2) * 2;
                uint32_t adrA = (qg * 16 + g) * PSTR + cb;
                uint32_t adrB = (qg * 16 + g + 8) * PSTR + cb;
                *(uint32_t*)(sma + A_PH + adrA) = pack_bf16(__bfloat162float(h0), __bfloat162float(h1));
                *(uint32_t*)(sma + A_PH + adrB) = pack_bf16(__bfloat162float(h2), __bfloat162float(h3));
                *(uint32_t*)(sma + A_PL + adrA) = pack_bf16(l0, l1);
                *(uint32_t*)(sma + A_PL + adrB) = pack_bf16(l2, l3);
            }
            sA += __shfl_xor_sync(0xffffffffu, sA, 1);
            sA += __shfl_xor_sync(0xffffffffu, sA, 2);
            sB += __shfl_xor_sync(0xffffffffu, sB, 1);
            sB += __shfl_xor_sync(0xffffffffu, sB, 2);
            if (t4 == 0) {
                psum[kvh * 64 + qg * 16 + g] = sA;
                psum[kvh * 64 + qg * 16 + g + 8] = sB;
            }
        }
        CP_WAIT(0);
        __syncthreads();

        if (tid < 64)
            lrow[tid] = lrow[tid] * corr[tid] + psum[tid] + psum[64 + tid];

        {
            float cA = corr[qg * 16 + g];
            float cB = corr[qg * 16 + g + 8];
            #pragma unroll
            for (int nt = 0; nt < 16; nt++) {
                o[nt][0] *= cA; o[nt][1] *= cA;
                o[nt][2] *= cB; o[nt][3] *= cB;
            }
        }
        #pragma unroll
        for (int ks = 0; ks < 4; ks++) {
            uint32_t pah[4], pal[4];
            ldsm_x4(pah[0], pah[1], pah[2], pah[3],
                    sb + A_PH + (qg * 16 + arow) * PSTR + ks * 32 + aoff);
            ldsm_x4(pal[0], pal[1], pal[2], pal[3],
                    sb + A_PL + (qg * 16 + arow) * PSTR + ks * 32 + aoff);
            #pragma unroll
            for (int np = 0; np < 8; np++) {
                int col = dh * 128 + np * 16 + vcoff;
                uint32_t vrowg = (ks * 16 + vrow) * QSTR + col * 2;
                uint32_t vh0, vh1, vh2, vh3, vl0, vl1, vl2, vl3;
                ldsm_x4_t(vh0, vh1, vh2, vh3, sb + A_VH + vrowg);
                ldsm_x4_t(vl0, vl1, vl2, vl3, sb + A_VL + vrowg);
                mma_bf16(o[np * 2], pah[0], pah[1], pah[2], pah[3], vh0, vh1);
                mma_bf16(o[np * 2], pah[0], pah[1], pah[2], pah[3], vl0, vl1);
                mma_bf16(o[np * 2], pal[0], pal[1], pal[2], pal[3], vh0, vh1);
                mma_bf16(o[np * 2 + 1], pah[0], pah[1], pah[2], pah[3], vh2, vh3);
                mma_bf16(o[np * 2 + 1], pah[0], pah[1], pah[2], pah[3], vl2, vl3);
                mma_bf16(o[np * 2 + 1], pal[0], pal[1], pal[2], pal[3], vh2, vh3);
            }
        }
    }

    __syncthreads();
    {
        float invA = 1.0f / lrow[qg * 16 + g];
        float invB = 1.0f / lrow[qg * 16 + g + 8];
        size_t rowA = (size_t)(b * SEQ + q0 + qg * 16 + g) * HIDDEN;
        size_t rowB = rowA + (size_t)8 * HIDDEN;
        int colbase = h * 256 + dh * 128 + t4 * 2;
        #pragma unroll
        for (int nt = 0; nt < 16; nt++) {
            int col = colbase + nt * 8;
            float a0 = o[nt][0] * invA, a1 = o[nt][1] * invA;
            float b0 = o[nt][2] * invB, b1 = o[nt][3] * invB;
            __nv_bfloat16 ha0 = __float2bfloat16(a0), ha1 = __float2bfloat16(a1);
            __nv_bfloat16 hb0 = __float2bfloat16(b0), hb1 = __float2bfloat16(b1);
            *(uint32_t*)(Oh + rowA + col) = pack_bf16(__bfloat162float(ha0), __bfloat162float(ha1));
            *(uint32_t*)(Ol + rowA + col) = pack_bf16(a0 - __bfloat162float(ha0), a1 - __bfloat162float(ha1));
            *(uint32_t*)(Oh + rowB + col) = pack_bf16(__bfloat162float(hb0), __bfloat162float(hb1));
            *(uint32_t*)(Ol + rowB + col) = pack_bf16(b0 - __bfloat162float(hb0), b1 - __bfloat162float(hb1));
        }
    }
}

// ============================================================================
// Launch
// ============================================================================
extern "C" void kernel_launch(void* const* d_in, const int* in_sizes, int n_in,
                              void* d_out, int out_size)
{
    const float* X   = (const float*)d_in[0];
    const float* msk = (const float*)d_in[1];
    const int*   pos = (const int*)  d_in[2];
    const float* Wq  = (const float*)d_in[3];
    const float* Wk  = (const float*)d_in[4];
    const float* Wv  = (const float*)d_in[5];
    const float* Wo  = (const float*)d_in[6];
    float* out = (float*)d_out;

    __nv_bfloat16* bf = nullptr;
    cudaGetSymbolAddress((void**)&bf, g_bf16);

    __nv_bfloat16* Xh   = bf + 0 * SLOT;
    __nv_bfloat16* Xl   = bf + 1 * SLOT;
    __nv_bfloat16* Oh   = bf + 2 * SLOT;
    __nv_bfloat16* Ol   = bf + 3 * SLOT;
    __nv_bfloat16* WqkvH = bf + 4 * SLOT;   // 12288 x 4096
    __nv_bfloat16* WqkvL = bf + 7 * SLOT;
    __nv_bfloat16* Woh  = bf + 10 * SLOT;
    __nv_bfloat16* Wol  = bf + 11 * SLOT;
    __nv_bfloat16* Qh   = bf + 12 * SLOT;
    __nv_bfloat16* Ql   = bf + 13 * SLOT;
    __nv_bfloat16* Kh   = bf + 14 * SLOT;
    __nv_bfloat16* Kl   = bf + 15 * SLOT;
    __nv_bfloat16* Vh   = bf + 16 * SLOT;
    __nv_bfloat16* Vl   = bf + 17 * SLOT;

    int split_blocks = (int)(SLOT / (256 * 4));
    split_rows_kernel<<<split_blocks, 256>>>(X, Xh, Xl);
    dim3 tgrid(HIDDEN / 32, HIDDEN / 32);
    split_T_kernel<<<tgrid, 256>>>(Wq, WqkvH, WqkvL);
    split_T_kernel<<<tgrid, 256>>>(Wk, WqkvH + (size_t)4096 * HIDDEN, WqkvL + (size_t)4096 * HIDDEN);
    split_T_kernel<<<tgrid, 256>>>(Wv, WqkvH + (size_t)8192 * HIDDEN, WqkvL + (size_t)8192 * HIDDEN);
    split_T_kernel<<<tgrid, 256>>>(Wo, Woh, Wol);

    int gsmem = 2 * STAGE_B;   // 81920
    cudaFuncSetAttribute(gemm_qkv_kernel,
                         cudaFuncAttributeMaxDynamicSharedMemorySize, gsmem);
    cudaFuncSetAttribute(gemm_mma_kernel,
                         cudaFuncAttributeMaxDynamicSharedMemorySize, gsmem);

    // one merged QKV GEMM (N = 12288) with fused rope/scale/split epilogue
    dim3 qkvgrid(3 * HIDDEN / 128, MROWS / 128);   // (96, 32)
    gemm_qkv_kernel<<<qkvgrid, 256, gsmem>>>(Xh, Xl, WqkvH, WqkvL, pos,
                                             Qh, Ql, Kh, Kl, Vh, Vl);

    cudaFuncSetAttribute(attn_mma_kernel,
                         cudaFuncAttributeMaxDynamicSharedMemorySize, A_SMEM_TOTAL);
    dim3 agrid(SEQ / AQ, NHEADS, BATCH);
    attn_mma_kernel<<<agrid, 256, A_SMEM_TOTAL>>>(Qh, Ql, Kh, Kl, Vh, Vl, msk, Oh, Ol);

    dim3 ogrid(HIDDEN / 128, MROWS / 128);   // (32, 32)
    gemm_mma_kernel<<<ogrid, 256, gsmem>>>(Oh, Ol, Woh, Wol, out);
}